// round 10
// baseline (speedup 1.0000x reference)
#include <cuda_runtime.h>
#include <cstdint>

#define BB 4
#define CC 256
#define NQ 4225        // 65*65
#define NCO 192        // 128 shortcut + 64 q
#define MPAD 1920      // 1728 conv + 64 k + 64 v, padded to 15*128
#define NTOT 4096      // 4 b * 1024 p

typedef unsigned long long ull;

// ---------------- scratch (device globals; no allocation allowed) ------------
__device__ float g_xrT[BB * 1024 * CC];       // BN+ReLU, transposed [b][p][c] (tf32-rounded)
__device__ float g_wA[MPAD * CC];             // GEMM A rows: conv taps (flipped) + wk + wv
__device__ float g_Y[MPAD * NTOT];            // GEMM result [m][n=b*1024+p]
__device__ float g_q[BB * 64 * NQ];           // q conv output  [b][d][n]
__device__ float g_attO[BB * 64 * NQ];        // attention out  [b][d][n]

// ---------------- helpers ----------------------------------------------------
__device__ __forceinline__ ull pk2(float a, float b) {
    ull r; asm("mov.b64 %0, {%1,%2};" : "=l"(r) : "f"(a), "f"(b)); return r;
}
__device__ __forceinline__ void upk2(ull v, float& a, float& b) {
    asm("mov.b64 {%0,%1}, %2;" : "=f"(a), "=f"(b) : "l"(v));
}
__device__ __forceinline__ ull ffma2(ull a, ull b, ull c) {
    ull r; asm("fma.rn.f32x2 %0, %1, %2, %3;" : "=l"(r) : "l"(a), "l"(b), "l"(c)); return r;
}
__device__ __forceinline__ float ex2f(float x) {
    float r; asm("ex2.approx.f32 %0, %1;" : "=f"(r) : "f"(x)); return r;
}
__device__ __forceinline__ float tf32r(float x) {   // round-to-nearest tf32
    float r; asm("cvt.rna.tf32.f32 %0, %1;" : "=f"(r) : "f"(x)); return r;
}
__device__ __forceinline__ uint32_t smem_u32(const void* p) {
    return (uint32_t)__cvta_generic_to_shared(p);
}
__device__ __forceinline__ void cpasync16(uint32_t saddr, const void* g) {
    asm volatile("cp.async.cg.shared.global [%0], [%1], 16;" :: "r"(saddr), "l"(g));
}
#define CP_COMMIT() asm volatile("cp.async.commit_group;" ::: "memory")
#define CP_WAIT(n)  asm volatile("cp.async.wait_group %0;" :: "n"(n) : "memory")

// mma.sync m16n8k8 tf32. Frag layouts (PTX, verified R7/R8):
//  A: a0=(g,tg) a1=(g+8,tg) a2=(g,tg+4) a3=(g+8,tg+4)
//  B: b0=(k=tg, n=g) b1=(k=tg+4, n=g)
//  C: c0=(g,2tg) c1=(g,2tg+1) c2=(g+8,2tg) c3=(g+8,2tg+1)
__device__ __forceinline__ void mma_acc(float* d, const uint32_t* a, uint32_t b0, uint32_t b1) {
    asm volatile(
        "mma.sync.aligned.m16n8k8.row.col.f32.tf32.tf32.f32 "
        "{%0,%1,%2,%3}, {%4,%5,%6,%7}, {%8,%9}, {%0,%1,%2,%3};"
        : "+f"(d[0]), "+f"(d[1]), "+f"(d[2]), "+f"(d[3])
        : "r"(a[0]), "r"(a[1]), "r"(a[2]), "r"(a[3]), "r"(b0), "r"(b1));
}
__device__ __forceinline__ void mma_z(float* d, const uint32_t* a, uint32_t b0, uint32_t b1) {
    asm volatile(
        "mma.sync.aligned.m16n8k8.row.col.f32.tf32.tf32.f32 "
        "{%0,%1,%2,%3}, {%4,%5,%6,%7}, {%8,%9}, {%10,%11,%12,%13};"
        : "=f"(d[0]), "=f"(d[1]), "=f"(d[2]), "=f"(d[3])
        : "r"(a[0]), "r"(a[1]), "r"(a[2]), "r"(a[3]), "r"(b0), "r"(b1),
          "f"(0.f), "f"(0.f), "f"(0.f), "f"(0.f));
}
__device__ __forceinline__ void mma8(float* d, const uint32_t* a, const uint32_t* b) {
    asm volatile(
        "mma.sync.aligned.m16n8k8.row.col.f32.tf32.tf32.f32 "
        "{%0,%1,%2,%3}, {%4,%5,%6,%7}, {%8,%9}, {%0,%1,%2,%3};"
        : "+f"(d[0]), "+f"(d[1]), "+f"(d[2]), "+f"(d[3])
        : "r"(a[0]), "r"(a[1]), "r"(a[2]), "r"(a[3]), "r"(b[0]), "r"(b[1]));
}

// ---------------- kernel 1: BN + ReLU + transpose -> xrT[b][p][c] (tf32) -----
__global__ void __launch_bounds__(256) bnT_kernel(
    const float* __restrict__ x, const float* __restrict__ gamma,
    const float* __restrict__ beta, const float* __restrict__ rmean,
    const float* __restrict__ rvar)
{
    __shared__ float s[32][33];
    const int pb = blockIdx.x, cb = blockIdx.y, b = blockIdx.z;
    const int tx = threadIdx.x, ty = threadIdx.y;     // 32 x 8
#pragma unroll
    for (int k = 0; k < 4; k++) {
        int cl = ty + k * 8;
        int c = cb * 32 + cl;
        float a = gamma[c] * rsqrtf(rvar[c] + 1e-5f);
        float bia = beta[c] - rmean[c] * a;
        float v = fmaxf(fmaf(x[(b * 256 + c) * 1024 + pb * 32 + tx], a, bia), 0.f);
        s[cl][tx] = v;
    }
    __syncthreads();
#pragma unroll
    for (int k = 0; k < 4; k++) {
        int pl = ty + k * 8;
        int p = pb * 32 + pl;
        g_xrT[(b * 1024 + p) * 256 + cb * 32 + tx] = tf32r(s[tx][pl]);
    }
}

// ---------------- kernel 2: pack A rows: conv taps (flipped) + wk + wv -------
__global__ void __launch_bounds__(256) wpack_kernel(
    const float* __restrict__ w_sc, const float* __restrict__ w_q,
    const float* __restrict__ w_k, const float* __restrict__ w_v)
{
    int i = blockIdx.x * 256 + threadIdx.x;           // [0, 1920*256)
    int m = i >> 8, c = i & 255;
    float v = 0.f;
    if (m < 1728) {
        int t = m / NCO, co = m - t * NCO;
        int s = 8 - t;                                 // spatial flip (verified)
        if (co < 128) v = w_sc[(c * 128 + co) * 9 + s];
        else          v = w_q[(c * 64 + (co - 128)) * 9 + s];
    } else if (m < 1792) {
        v = w_k[(m - 1728) * 256 + c];
    } else if (m < 1856) {
        v = w_v[(m - 1792) * 256 + c];
    }
    g_wA[i] = tf32r(v);
}

// ---------------- kernel 3: cp.async double-buffered tf32 GEMM ---------------
// Y = [Wconv;Wk;Wv] x X^T. Block 128x128, 8 warps (2m x 4n).
// K=256 in 16 chunks of 16, 2-stage cp.async pipeline. SSTR=20 (bank-clean).
#define SSTR 20
__global__ void __launch_bounds__(256) gemm_kernel() {
    __shared__ __align__(16) float As[2][128 * SSTR];
    __shared__ __align__(16) float Bs[2][128 * SSTR];
    const int tid = threadIdx.x;
    const int wid = tid >> 5, lane = tid & 31;
    const int nt = blockIdx.x, mt = blockIdx.y;
    const int wm = wid & 1, wn = wid >> 1;            // 2 x 4
    const int g = lane >> 2, tg = lane & 3;

    // loader mapping: 512 float4 per array per stage, 2 per thread
    const int lrow0 = tid >> 2, lq0 = tid & 3;        // rows 0..63
    const int lrow1 = lrow0 + 64;

    auto load_stage = [&](int kc, int buf) {
        const float* ga0 = g_wA + (size_t)(mt * 128 + lrow0) * 256 + kc * 16 + lq0 * 4;
        const float* ga1 = g_wA + (size_t)(mt * 128 + lrow1) * 256 + kc * 16 + lq0 * 4;
        const float* gb0 = g_xrT + (size_t)(nt * 128 + lrow0) * 256 + kc * 16 + lq0 * 4;
        const float* gb1 = g_xrT + (size_t)(nt * 128 + lrow1) * 256 + kc * 16 + lq0 * 4;
        cpasync16(smem_u32(&As[buf][lrow0 * SSTR + lq0 * 4]), ga0);
        cpasync16(smem_u32(&As[buf][lrow1 * SSTR + lq0 * 4]), ga1);
        cpasync16(smem_u32(&Bs[buf][lrow0 * SSTR + lq0 * 4]), gb0);
        cpasync16(smem_u32(&Bs[buf][lrow1 * SSTR + lq0 * 4]), gb1);
    };

    float acc[4][4][4];
#pragma unroll
    for (int mi = 0; mi < 4; mi++)
#pragma unroll
        for (int ni = 0; ni < 4; ni++)
#pragma unroll
            for (int q = 0; q < 4; q++) acc[mi][ni][q] = 0.f;

    load_stage(0, 0);
    CP_COMMIT();

    for (int kc = 0; kc < 16; kc++) {
        const int buf = kc & 1;
        if (kc + 1 < 16) {
            load_stage(kc + 1, buf ^ 1);
            CP_COMMIT();
            CP_WAIT(1);
        } else {
            CP_WAIT(0);
        }
        __syncthreads();

#pragma unroll
        for (int ks = 0; ks < 2; ks++) {
            uint32_t a[4][4], b[4][2];
#pragma unroll
            for (int mi = 0; mi < 4; mi++) {
                const float* ap = &As[buf][(wm * 64 + mi * 16) * SSTR + ks * 8];
                a[mi][0] = __float_as_uint(ap[g * SSTR + tg]);
                a[mi][1] = __float_as_uint(ap[(g + 8) * SSTR + tg]);
                a[mi][2] = __float_as_uint(ap[g * SSTR + tg + 4]);
                a[mi][3] = __float_as_uint(ap[(g + 8) * SSTR + tg + 4]);
            }
#pragma unroll
            for (int ni = 0; ni < 4; ni++) {
                const float* bp = &Bs[buf][(wn * 32 + ni * 8) * SSTR + ks * 8];
                b[ni][0] = __float_as_uint(bp[g * SSTR + tg]);
                b[ni][1] = __float_as_uint(bp[g * SSTR + tg + 4]);
            }
#pragma unroll
            for (int mi = 0; mi < 4; mi++)
#pragma unroll
                for (int ni = 0; ni < 4; ni++)
                    mma8(acc[mi][ni], a[mi], b[ni]);
        }
        __syncthreads();   // all reads of buf done before it is refilled (kc+2)
    }

#pragma unroll
    for (int mi = 0; mi < 4; mi++) {
#pragma unroll
        for (int ni = 0; ni < 4; ni++) {
            int row0 = mt * 128 + wm * 64 + mi * 16 + g;
            int col  = nt * 128 + wn * 32 + ni * 8 + 2 * tg;
            float2 v0 = make_float2(acc[mi][ni][0], acc[mi][ni][1]);
            float2 v1 = make_float2(acc[mi][ni][2], acc[mi][ni][3]);
            *(float2*)(g_Y + (size_t)row0 * NTOT + col) = v0;
            *(float2*)(g_Y + (size_t)(row0 + 8) * NTOT + col) = v1;
        }
    }
}

// ---------------- kernel 4: tap-gather  Y -> out(shortcut) + g_q -------------
// block (65,4): x = threadIdx.x (no integer division anywhere).
__global__ void __launch_bounds__(260) gather_kernel(float* __restrict__ out) {
    const int y = blockIdx.x, b = blockIdx.y, zg = blockIdx.z;
    const int x = threadIdx.x;                         // 0..64
    const int ty = threadIdx.y;                        // 0..3

    int tys[2], iys[2], nyy = 0;
    if (y & 1) { tys[0] = 1; iys[0] = y >> 1; nyy = 1; }
    else {
        if ((y >> 1) <= 31)    { tys[nyy] = 0; iys[nyy] = y >> 1;       nyy++; }
        if ((y >> 1) - 1 >= 0) { tys[nyy] = 2; iys[nyy] = (y >> 1) - 1; nyy++; }
    }
    int txs[2], ixs[2], nxx = 0;
    if (x & 1) { txs[0] = 1; ixs[0] = x >> 1; nxx = 1; }
    else {
        if ((x >> 1) <= 31)    { txs[nxx] = 0; ixs[nxx] = x >> 1;       nxx++; }
        if ((x >> 1) - 1 >= 0) { txs[nxx] = 2; ixs[nxx] = (x >> 1) - 1; nxx++; }
    }
    const int n = y * 65 + x;

#pragma unroll
    for (int i = 0; i < 6; i++) {
        int co = zg * 24 + i * 4 + ty;
        float s = 0.f;
        for (int yi = 0; yi < nyy; yi++)
            for (int xi = 0; xi < nxx; xi++) {
                int t = tys[yi] * 3 + txs[xi];
                s += __ldg(g_Y + (size_t)(t * NCO + co) * NTOT + b * 1024 + iys[yi] * 32 + ixs[xi]);
            }
        if (co < 128) out[(size_t)(b * 128 + co) * NQ + n] = s;
        else          g_q[(size_t)(b * 64 + (co - 128)) * NQ + n] = s;
    }
}

// ---------------- kernel 5: tensor-core attention, shuffle-relayout P --------
// CTA = 128 q rows x one (b,h); warp = 16 q rows. 8 chunks of 128 keys.
__global__ void __launch_bounds__(256) attn2_kernel() {
    __shared__ float sKc[128 * 9];
    __shared__ float sVc[128 * 9];
    const int qt = blockIdx.x, h = blockIdx.y, b = blockIdx.z;
    const int tid = threadIdx.x, wid = tid >> 5, lane = tid & 31;
    const int g = lane >> 2, tg = lane & 3;
    const int n0 = qt * 128 + wid * 16;
    const float sc = 0.35355339059327373f * 1.4426950408889634f;  // 1/sqrt(dk)*log2(e)

    uint32_t qf[4];
    {
        const float* qb = g_q + (size_t)(b * 64 + h * 8) * NQ;
        int nA = n0 + g, nB = n0 + 8 + g;
        float v0 = (nA < NQ) ? tf32r(qb[(size_t)tg * NQ + nA] * sc) : 0.f;
        float v1 = (nB < NQ) ? tf32r(qb[(size_t)tg * NQ + nB] * sc) : 0.f;
        float v2 = (nA < NQ) ? tf32r(qb[(size_t)(tg + 4) * NQ + nA] * sc) : 0.f;
        float v3 = (nB < NQ) ? tf32r(qb[(size_t)(tg + 4) * NQ + nB] * sc) : 0.f;
        qf[0] = __float_as_uint(v0); qf[1] = __float_as_uint(v1);
        qf[2] = __float_as_uint(v2); qf[3] = __float_as_uint(v3);
    }

    float oacc[4] = {0.f, 0.f, 0.f, 0.f};
    float lacc[4] = {0.f, 0.f, 0.f, 0.f};
    const uint32_t one = 0x3f800000u;
    const int src0 = g * 4 + (tg >> 1);
    const int src2 = src0 + 2;
    const bool e = tg & 1;

    const int dld = tid >> 5;                          // 0..7
    const int kq = (tid & 31) * 4;                     // 0..124
    const float* srcK = g_Y + (size_t)(1728 + h * 8 + dld) * NTOT + b * 1024 + kq;
    const float* srcV = g_Y + (size_t)(1792 + h * 8 + dld) * NTOT + b * 1024 + kq;

    for (int ch = 0; ch < 8; ch++) {
        __syncthreads();
        {
            float4 k4 = *(const float4*)(srcK + ch * 128);
            sKc[(kq + 0) * 9 + dld] = tf32r(k4.x);
            sKc[(kq + 1) * 9 + dld] = tf32r(k4.y);
            sKc[(kq + 2) * 9 + dld] = tf32r(k4.z);
            sKc[(kq + 3) * 9 + dld] = tf32r(k4.w);
            float4 v4 = *(const float4*)(srcV + ch * 128);
            sVc[(kq + 0) * 9 + dld] = tf32r(v4.x);
            sVc[(kq + 1) * 9 + dld] = tf32r(v4.y);
            sVc[(kq + 2) * 9 + dld] = tf32r(v4.z);
            sVc[(kq + 3) * 9 + dld] = tf32r(v4.w);
        }
        __syncthreads();

#pragma unroll
        for (int kk = 0; kk < 16; kk++) {
            // S block = Q x K^T  (16q x 8k)
            uint32_t kf0 = __float_as_uint(sKc[(kk * 8 + g) * 9 + tg]);
            uint32_t kf1 = __float_as_uint(sKc[(kk * 8 + g) * 9 + tg + 4]);
            float s[4];
            mma_z(s, qf, kf0, kf1);
            float p0 = ex2f(s[0]), p1 = ex2f(s[1]);
            float p2 = ex2f(s[2]), p3 = ex2f(s[3]);
            // C-frag -> A-frag lane permutation
            float q00 = __shfl_sync(0xffffffffu, p0, src0);
            float q01 = __shfl_sync(0xffffffffu, p1, src0);
            float q02 = __shfl_sync(0xffffffffu, p2, src0);
            float q03 = __shfl_sync(0xffffffffu, p3, src0);
            float q20 = __shfl_sync(0xffffffffu, p0, src2);
            float q21 = __shfl_sync(0xffffffffu, p1, src2);
            float q22 = __shfl_sync(0xffffffffu, p2, src2);
            float q23 = __shfl_sync(0xffffffffu, p3, src2);
            uint32_t af[4];
            af[0] = __float_as_uint(e ? q01 : q00);
            af[1] = __float_as_uint(e ? q03 : q02);
            af[2] = __float_as_uint(e ? q21 : q20);
            af[3] = __float_as_uint(e ? q23 : q22);
            // O += P V ; L += P * ones (same frags)
            uint32_t vb0 = __float_as_uint(sVc[(kk * 8 + tg) * 9 + g]);
            uint32_t vb1 = __float_as_uint(sVc[(kk * 8 + tg + 4) * 9 + g]);
            mma_acc(oacc, af, vb0, vb1);
            mma_acc(lacc, af, one, one);
        }
    }

    // epilogue: normalize, store (C layout: rows g/g+8, cols 2tg/2tg+1 = d)
    float* ob = g_attO + (size_t)(b * 64 + h * 8) * NQ;
    int nA = n0 + g, nB = n0 + 8 + g;
    if (nA < NQ) {
        float inv = 1.f / lacc[0];
        ob[(size_t)(2 * tg) * NQ + nA]     = oacc[0] * inv;
        ob[(size_t)(2 * tg + 1) * NQ + nA] = oacc[1] * inv;
    }
    if (nB < NQ) {
        float inv = 1.f / lacc[2];
        ob[(size_t)(2 * tg) * NQ + nB]     = oacc[2] * inv;
        ob[(size_t)(2 * tg + 1) * NQ + nB] = oacc[3] * inv;
    }
}

// ---------------- kernel 6: output projection + residual add -----------------
__global__ void __launch_bounds__(256) proj_kernel(
    const float* __restrict__ w_o, float* __restrict__ out)
{
    __shared__ float sw[32 * 64];
    const int cog = blockIdx.z, b = blockIdx.y;
    for (int i = threadIdx.x; i < 2048; i += 256) sw[i] = w_o[cog * 2048 + i];
    __syncthreads();

    const int nl = threadIdx.x & 63;
    const int sub = threadIdx.x >> 6;                  // 0..3 (8 co each)
    const int n = blockIdx.x * 64 + nl;
    if (n >= NQ) return;

    ull a2[32];
#pragma unroll
    for (int dd = 0; dd < 32; dd++) {
        float a0 = g_attO[(size_t)(b * 64 + 2 * dd) * NQ + n];
        float a1 = g_attO[(size_t)(b * 64 + 2 * dd + 1) * NQ + n];
        a2[dd] = pk2(a0, a1);
    }

#pragma unroll
    for (int c0 = 0; c0 < 8; c0++) {
        int cl = sub * 8 + c0;
        const ull* wr = (const ull*)(sw + cl * 64);
        ull s2 = 0ull;
#pragma unroll
        for (int dd = 0; dd < 32; dd++)
            s2 = ffma2(a2[dd], wr[dd], s2);
        float s0, s1; upk2(s2, s0, s1);
        int co = cog * 32 + cl;
        out[(size_t)(b * 128 + co) * NQ + n] += s0 + s1;
    }
}

// ---------------- launcher ---------------------------------------------------
extern "C" void kernel_launch(void* const* d_in, const int* in_sizes, int n_in,
                              void* d_out, int out_size)
{
    const float* x     = (const float*)d_in[0];
    const float* gamma = (const float*)d_in[1];
    const float* beta  = (const float*)d_in[2];
    const float* rmean = (const float*)d_in[3];
    const float* rvar  = (const float*)d_in[4];
    const float* w_sc  = (const float*)d_in[5];
    const float* w_q   = (const float*)d_in[6];
    const float* w_k   = (const float*)d_in[7];
    const float* w_v   = (const float*)d_in[8];
    const float* w_o   = (const float*)d_in[9];
    float* out = (float*)d_out;

    bnT_kernel<<<dim3(32, 8, 4), dim3(32, 8)>>>(x, gamma, beta, rmean, rvar);
    wpack_kernel<<<1920, 256>>>(w_sc, w_q, w_k, w_v);
    gemm_kernel<<<dim3(32, 15), 256>>>();
    gather_kernel<<<dim3(65, 4, 8), dim3(65, 4)>>>(out);
    attn2_kernel<<<dim3(34, 8, 4), 256>>>();
    proj_kernel<<<dim3(67, 4, 4), 256>>>(w_o, out);
}

// round 11
// speedup vs baseline: 1.0231x; 1.0231x over previous
#include <cuda_runtime.h>
#include <cstdint>

#define BB 4
#define CC 256
#define NQ 4225        // 65*65
#define NCO 192        // 128 shortcut + 64 q
#define MPAD 1920      // 1728 conv + 64 k + 64 v, padded to 15*128
#define NTOT 4096      // 4 b * 1024 p

typedef unsigned long long ull;

// ---------------- scratch (device globals; no allocation allowed) ------------
__device__ float g_xrT[BB * 1024 * CC];       // BN+ReLU, transposed [b][p][c] (tf32-rounded)
__device__ float g_wA[MPAD * CC];             // GEMM A rows: conv taps (flipped) + wk + wv
__device__ float g_Y[MPAD * NTOT];            // GEMM result [m][n=b*1024+p]
__device__ float g_q[BB * 64 * NQ];           // q conv output  [b][d][n]
__device__ float g_attO[BB * 64 * NQ];        // attention out  [b][d][n]

// ---------------- helpers ----------------------------------------------------
__device__ __forceinline__ ull pk2(float a, float b) {
    ull r; asm("mov.b64 %0, {%1,%2};" : "=l"(r) : "f"(a), "f"(b)); return r;
}
__device__ __forceinline__ void upk2(ull v, float& a, float& b) {
    asm("mov.b64 {%0,%1}, %2;" : "=f"(a), "=f"(b) : "l"(v));
}
__device__ __forceinline__ ull ffma2(ull a, ull b, ull c) {
    ull r; asm("fma.rn.f32x2 %0, %1, %2, %3;" : "=l"(r) : "l"(a), "l"(b), "l"(c)); return r;
}
__device__ __forceinline__ float ex2f(float x) {
    float r; asm("ex2.approx.f32 %0, %1;" : "=f"(r) : "f"(x)); return r;
}
__device__ __forceinline__ float tf32r(float x) {   // round-to-nearest tf32
    float r; asm("cvt.rna.tf32.f32 %0, %1;" : "=f"(r) : "f"(x)); return r;
}
__device__ __forceinline__ uint32_t smem_u32(const void* p) {
    return (uint32_t)__cvta_generic_to_shared(p);
}
__device__ __forceinline__ void cpasync16(uint32_t saddr, const void* g) {
    asm volatile("cp.async.cg.shared.global [%0], [%1], 16;" :: "r"(saddr), "l"(g));
}
#define CP_COMMIT() asm volatile("cp.async.commit_group;" ::: "memory")
#define CP_WAIT(n)  asm volatile("cp.async.wait_group %0;" :: "n"(n) : "memory")

// mma.sync m16n8k8 tf32. Frag layouts (PTX, verified R7/R8):
//  A: a0=(g,tg) a1=(g+8,tg) a2=(g,tg+4) a3=(g+8,tg+4)
//  B: b0=(k=tg, n=g) b1=(k=tg+4, n=g)
//  C: c0=(g,2tg) c1=(g,2tg+1) c2=(g+8,2tg) c3=(g+8,2tg+1)
__device__ __forceinline__ void mma_acc(float* d, const uint32_t* a, uint32_t b0, uint32_t b1) {
    asm volatile(
        "mma.sync.aligned.m16n8k8.row.col.f32.tf32.tf32.f32 "
        "{%0,%1,%2,%3}, {%4,%5,%6,%7}, {%8,%9}, {%0,%1,%2,%3};"
        : "+f"(d[0]), "+f"(d[1]), "+f"(d[2]), "+f"(d[3])
        : "r"(a[0]), "r"(a[1]), "r"(a[2]), "r"(a[3]), "r"(b0), "r"(b1));
}
__device__ __forceinline__ void mma_z(float* d, const uint32_t* a, uint32_t b0, uint32_t b1) {
    asm volatile(
        "mma.sync.aligned.m16n8k8.row.col.f32.tf32.tf32.f32 "
        "{%0,%1,%2,%3}, {%4,%5,%6,%7}, {%8,%9}, {%10,%11,%12,%13};"
        : "=f"(d[0]), "=f"(d[1]), "=f"(d[2]), "=f"(d[3])
        : "r"(a[0]), "r"(a[1]), "r"(a[2]), "r"(a[3]), "r"(b0), "r"(b1),
          "f"(0.f), "f"(0.f), "f"(0.f), "f"(0.f));
}
__device__ __forceinline__ void mma8(float* d, const uint32_t* a, const uint32_t* b) {
    asm volatile(
        "mma.sync.aligned.m16n8k8.row.col.f32.tf32.tf32.f32 "
        "{%0,%1,%2,%3}, {%4,%5,%6,%7}, {%8,%9}, {%0,%1,%2,%3};"
        : "+f"(d[0]), "+f"(d[1]), "+f"(d[2]), "+f"(d[3])
        : "r"(a[0]), "r"(a[1]), "r"(a[2]), "r"(a[3]), "r"(b[0]), "r"(b[1]));
}

// ---------------- kernel 1: fused prep (bnT + wpack), branch on blockIdx -----
// blocks [0,1024): BN+ReLU+transpose -> xrT.  blocks [1024,2944): weight pack.
__global__ void __launch_bounds__(256) prep_kernel(
    const float* __restrict__ x, const float* __restrict__ gamma,
    const float* __restrict__ beta, const float* __restrict__ rmean,
    const float* __restrict__ rvar,
    const float* __restrict__ w_sc, const float* __restrict__ w_q,
    const float* __restrict__ w_k, const float* __restrict__ w_v)
{
    __shared__ float s[32][33];
    const int bx = blockIdx.x;
    const int tid = threadIdx.x;
    if (bx < 1024) {
        const int pb = bx & 31, cb = (bx >> 5) & 7, b = bx >> 8;
        const int tx = tid & 31, ty = tid >> 5;       // 32 x 8
#pragma unroll
        for (int k = 0; k < 4; k++) {
            int cl = ty + k * 8;
            int c = cb * 32 + cl;
            float a = gamma[c] * rsqrtf(rvar[c] + 1e-5f);
            float bia = beta[c] - rmean[c] * a;
            float v = fmaxf(fmaf(x[(b * 256 + c) * 1024 + pb * 32 + tx], a, bia), 0.f);
            s[cl][tx] = v;
        }
        __syncthreads();
#pragma unroll
        for (int k = 0; k < 4; k++) {
            int pl = ty + k * 8;
            int p = pb * 32 + pl;
            g_xrT[(b * 1024 + p) * 256 + cb * 32 + tx] = tf32r(s[tx][pl]);
        }
    } else {
        int i = (bx - 1024) * 256 + tid;              // [0, 1920*256)
        int m = i >> 8, c = i & 255;
        float v = 0.f;
        if (m < 1728) {
            int t = m / NCO, co = m - t * NCO;
            int sfl = 8 - t;                           // spatial flip (verified)
            if (co < 128) v = w_sc[(c * 128 + co) * 9 + sfl];
            else          v = w_q[(c * 64 + (co - 128)) * 9 + sfl];
        } else if (m < 1792) {
            v = w_k[(m - 1728) * 256 + c];
        } else if (m < 1856) {
            v = w_v[(m - 1792) * 256 + c];
        }
        g_wA[i] = tf32r(v);
    }
}

// ---------------- kernel 2: cp.async double-buffered tf32 GEMM ---------------
// Y = [Wconv;Wk;Wv] x X^T. Block 128x128, 8 warps (2m x 4n).
// K=256 in 16 chunks of 16, 2-stage cp.async pipeline. SSTR=20 (bank-clean).
#define SSTR 20
__global__ void __launch_bounds__(256) gemm_kernel() {
    __shared__ __align__(16) float As[2][128 * SSTR];
    __shared__ __align__(16) float Bs[2][128 * SSTR];
    const int tid = threadIdx.x;
    const int wid = tid >> 5, lane = tid & 31;
    const int nt = blockIdx.x, mt = blockIdx.y;
    const int wm = wid & 1, wn = wid >> 1;            // 2 x 4
    const int g = lane >> 2, tg = lane & 3;

    const int lrow0 = tid >> 2, lq0 = tid & 3;        // rows 0..63
    const int lrow1 = lrow0 + 64;

    auto load_stage = [&](int kc, int buf) {
        const float* ga0 = g_wA + (size_t)(mt * 128 + lrow0) * 256 + kc * 16 + lq0 * 4;
        const float* ga1 = g_wA + (size_t)(mt * 128 + lrow1) * 256 + kc * 16 + lq0 * 4;
        const float* gb0 = g_xrT + (size_t)(nt * 128 + lrow0) * 256 + kc * 16 + lq0 * 4;
        const float* gb1 = g_xrT + (size_t)(nt * 128 + lrow1) * 256 + kc * 16 + lq0 * 4;
        cpasync16(smem_u32(&As[buf][lrow0 * SSTR + lq0 * 4]), ga0);
        cpasync16(smem_u32(&As[buf][lrow1 * SSTR + lq0 * 4]), ga1);
        cpasync16(smem_u32(&Bs[buf][lrow0 * SSTR + lq0 * 4]), gb0);
        cpasync16(smem_u32(&Bs[buf][lrow1 * SSTR + lq0 * 4]), gb1);
    };

    float acc[4][4][4];
#pragma unroll
    for (int mi = 0; mi < 4; mi++)
#pragma unroll
        for (int ni = 0; ni < 4; ni++)
#pragma unroll
            for (int q = 0; q < 4; q++) acc[mi][ni][q] = 0.f;

    load_stage(0, 0);
    CP_COMMIT();

    for (int kc = 0; kc < 16; kc++) {
        const int buf = kc & 1;
        if (kc + 1 < 16) {
            load_stage(kc + 1, buf ^ 1);
            CP_COMMIT();
            CP_WAIT(1);
        } else {
            CP_WAIT(0);
        }
        __syncthreads();

#pragma unroll
        for (int ks = 0; ks < 2; ks++) {
            uint32_t a[4][4], b[4][2];
#pragma unroll
            for (int mi = 0; mi < 4; mi++) {
                const float* ap = &As[buf][(wm * 64 + mi * 16) * SSTR + ks * 8];
                a[mi][0] = __float_as_uint(ap[g * SSTR + tg]);
                a[mi][1] = __float_as_uint(ap[(g + 8) * SSTR + tg]);
                a[mi][2] = __float_as_uint(ap[g * SSTR + tg + 4]);
                a[mi][3] = __float_as_uint(ap[(g + 8) * SSTR + tg + 4]);
            }
#pragma unroll
            for (int ni = 0; ni < 4; ni++) {
                const float* bp = &Bs[buf][(wn * 32 + ni * 8) * SSTR + ks * 8];
                b[ni][0] = __float_as_uint(bp[g * SSTR + tg]);
                b[ni][1] = __float_as_uint(bp[g * SSTR + tg + 4]);
            }
#pragma unroll
            for (int mi = 0; mi < 4; mi++)
#pragma unroll
                for (int ni = 0; ni < 4; ni++)
                    mma8(acc[mi][ni], a[mi], b[ni]);
        }
        __syncthreads();   // all reads of buf done before it is refilled (kc+2)
    }

#pragma unroll
    for (int mi = 0; mi < 4; mi++) {
#pragma unroll
        for (int ni = 0; ni < 4; ni++) {
            int row0 = mt * 128 + wm * 64 + mi * 16 + g;
            int col  = nt * 128 + wn * 32 + ni * 8 + 2 * tg;
            float2 v0 = make_float2(acc[mi][ni][0], acc[mi][ni][1]);
            float2 v1 = make_float2(acc[mi][ni][2], acc[mi][ni][3]);
            *(float2*)(g_Y + (size_t)row0 * NTOT + col) = v0;
            *(float2*)(g_Y + (size_t)(row0 + 8) * NTOT + col) = v1;
        }
    }
}

// ---------------- kernel 3: tap-gather  Y -> out(shortcut) + g_q -------------
// block (65,4): x = threadIdx.x (no integer division anywhere).
__global__ void __launch_bounds__(260) gather_kernel(float* __restrict__ out) {
    const int y = blockIdx.x, b = blockIdx.y, zg = blockIdx.z;
    const int x = threadIdx.x;                         // 0..64
    const int ty = threadIdx.y;                        // 0..3

    int tys[2], iys[2], nyy = 0;
    if (y & 1) { tys[0] = 1; iys[0] = y >> 1; nyy = 1; }
    else {
        if ((y >> 1) <= 31)    { tys[nyy] = 0; iys[nyy] = y >> 1;       nyy++; }
        if ((y >> 1) - 1 >= 0) { tys[nyy] = 2; iys[nyy] = (y >> 1) - 1; nyy++; }
    }
    int txs[2], ixs[2], nxx = 0;
    if (x & 1) { txs[0] = 1; ixs[0] = x >> 1; nxx = 1; }
    else {
        if ((x >> 1) <= 31)    { txs[nxx] = 0; ixs[nxx] = x >> 1;       nxx++; }
        if ((x >> 1) - 1 >= 0) { txs[nxx] = 2; ixs[nxx] = (x >> 1) - 1; nxx++; }
    }
    const int n = y * 65 + x;

#pragma unroll
    for (int i = 0; i < 6; i++) {
        int co = zg * 24 + i * 4 + ty;
        float s = 0.f;
        for (int yi = 0; yi < nyy; yi++)
            for (int xi = 0; xi < nxx; xi++) {
                int t = tys[yi] * 3 + txs[xi];
                s += __ldg(g_Y + (size_t)(t * NCO + co) * NTOT + b * 1024 + iys[yi] * 32 + ixs[xi]);
            }
        if (co < 128) out[(size_t)(b * 128 + co) * NQ + n] = s;
        else          g_q[(size_t)(b * 64 + (co - 128)) * NQ + n] = s;
    }
}

// ---------------- kernel 4: tensor-core attention ----------------------------
// CTA = 128 q rows x one (b,h); warp = 16 q rows. 8 chunks of 128 keys.
// QK per 8-key block -> ex2 -> shuffle-relayout -> PV mma. Row sums taken
// directly from the C-fragment P values (scalar adds + 2 bfly at end) --
// no L-mma (33% fewer tensor ops than R9/R10).
__global__ void __launch_bounds__(256) attn2_kernel() {
    __shared__ float sKc[128 * 9];
    __shared__ float sVc[128 * 9];
    const int qt = blockIdx.x, h = blockIdx.y, b = blockIdx.z;
    const int tid = threadIdx.x, wid = tid >> 5, lane = tid & 31;
    const int g = lane >> 2, tg = lane & 3;
    const int n0 = qt * 128 + wid * 16;
    const float sc = 0.35355339059327373f * 1.4426950408889634f;  // 1/sqrt(dk)*log2(e)

    uint32_t qf[4];
    {
        const float* qb = g_q + (size_t)(b * 64 + h * 8) * NQ;
        int nA = n0 + g, nB = n0 + 8 + g;
        float v0 = (nA < NQ) ? tf32r(qb[(size_t)tg * NQ + nA] * sc) : 0.f;
        float v1 = (nB < NQ) ? tf32r(qb[(size_t)tg * NQ + nB] * sc) : 0.f;
        float v2 = (nA < NQ) ? tf32r(qb[(size_t)(tg + 4) * NQ + nA] * sc) : 0.f;
        float v3 = (nB < NQ) ? tf32r(qb[(size_t)(tg + 4) * NQ + nB] * sc) : 0.f;
        qf[0] = __float_as_uint(v0); qf[1] = __float_as_uint(v1);
        qf[2] = __float_as_uint(v2); qf[3] = __float_as_uint(v3);
    }

    float oacc[4] = {0.f, 0.f, 0.f, 0.f};
    float lsum0 = 0.f, lsum2 = 0.f;
    const int src0 = g * 4 + (tg >> 1);
    const int src2 = src0 + 2;
    const bool e = tg & 1;

    const int dld = tid >> 5;                          // 0..7
    const int kq = (tid & 31) * 4;                     // 0..124
    const float* srcK = g_Y + (size_t)(1728 + h * 8 + dld) * NTOT + b * 1024 + kq;
    const float* srcV = g_Y + (size_t)(1792 + h * 8 + dld) * NTOT + b * 1024 + kq;

    for (int ch = 0; ch < 8; ch++) {
        __syncthreads();
        {
            float4 k4 = *(const float4*)(srcK + ch * 128);
            sKc[(kq + 0) * 9 + dld] = tf32r(k4.x);
            sKc[(kq + 1) * 9 + dld] = tf32r(k4.y);
            sKc[(kq + 2) * 9 + dld] = tf32r(k4.z);
            sKc[(kq + 3) * 9 + dld] = tf32r(k4.w);
            float4 v4 = *(const float4*)(srcV + ch * 128);
            sVc[(kq + 0) * 9 + dld] = tf32r(v4.x);
            sVc[(kq + 1) * 9 + dld] = tf32r(v4.y);
            sVc[(kq + 2) * 9 + dld] = tf32r(v4.z);
            sVc[(kq + 3) * 9 + dld] = tf32r(v4.w);
        }
        __syncthreads();

#pragma unroll
        for (int kk = 0; kk < 16; kk++) {
            // S block = Q x K^T  (16q x 8k)
            uint32_t kf0 = __float_as_uint(sKc[(kk * 8 + g) * 9 + tg]);
            uint32_t kf1 = __float_as_uint(sKc[(kk * 8 + g) * 9 + tg + 4]);
            float s[4];
            mma_z(s, qf, kf0, kf1);
            float p0 = ex2f(s[0]), p1 = ex2f(s[1]);
            float p2 = ex2f(s[2]), p3 = ex2f(s[3]);
            // row sums straight from C-fragment (rows g / g+8)
            lsum0 += p0 + p1;
            lsum2 += p2 + p3;
            // C-frag -> A-frag lane permutation
            float q00 = __shfl_sync(0xffffffffu, p0, src0);
            float q01 = __shfl_sync(0xffffffffu, p1, src0);
            float q02 = __shfl_sync(0xffffffffu, p2, src0);
            float q03 = __shfl_sync(0xffffffffu, p3, src0);
            float q20 = __shfl_sync(0xffffffffu, p0, src2);
            float q21 = __shfl_sync(0xffffffffu, p1, src2);
            float q22 = __shfl_sync(0xffffffffu, p2, src2);
            float q23 = __shfl_sync(0xffffffffu, p3, src2);
            uint32_t af[4];
            af[0] = __float_as_uint(e ? q01 : q00);
            af[1] = __float_as_uint(e ? q03 : q02);
            af[2] = __float_as_uint(e ? q21 : q20);
            af[3] = __float_as_uint(e ? q23 : q22);
            // O += P V
            uint32_t vb0 = __float_as_uint(sVc[(kk * 8 + tg) * 9 + g]);
            uint32_t vb1 = __float_as_uint(sVc[(kk * 8 + tg + 4) * 9 + g]);
            mma_acc(oacc, af, vb0, vb1);
        }
    }

    // reduce row sums over the 4 tg-lanes of each row group
    lsum0 += __shfl_xor_sync(0xffffffffu, lsum0, 1);
    lsum0 += __shfl_xor_sync(0xffffffffu, lsum0, 2);
    lsum2 += __shfl_xor_sync(0xffffffffu, lsum2, 1);
    lsum2 += __shfl_xor_sync(0xffffffffu, lsum2, 2);

    // epilogue: normalize, store (C layout: rows g/g+8, cols 2tg/2tg+1 = d)
    float* ob = g_attO + (size_t)(b * 64 + h * 8) * NQ;
    int nA = n0 + g, nB = n0 + 8 + g;
    if (nA < NQ) {
        float inv = 1.f / lsum0;
        ob[(size_t)(2 * tg) * NQ + nA]     = oacc[0] * inv;
        ob[(size_t)(2 * tg + 1) * NQ + nA] = oacc[1] * inv;
    }
    if (nB < NQ) {
        float inv = 1.f / lsum2;
        ob[(size_t)(2 * tg) * NQ + nB]     = oacc[2] * inv;
        ob[(size_t)(2 * tg + 1) * NQ + nB] = oacc[3] * inv;
    }
}

// ---------------- kernel 5: output projection + residual add -----------------
__global__ void __launch_bounds__(256) proj_kernel(
    const float* __restrict__ w_o, float* __restrict__ out)
{
    __shared__ float sw[32 * 64];
    const int cog = blockIdx.z, b = blockIdx.y;
    for (int i = threadIdx.x; i < 2048; i += 256) sw[i] = w_o[cog * 2048 + i];
    __syncthreads();

    const int nl = threadIdx.x & 63;
    const int sub = threadIdx.x >> 6;                  // 0..3 (8 co each)
    const int n = blockIdx.x * 64 + nl;
    if (n >= NQ) return;

    ull a2[32];
#pragma unroll
    for (int dd = 0; dd < 32; dd++) {
        float a0 = g_attO[(size_t)(b * 64 + 2 * dd) * NQ + n];
        float a1 = g_attO[(size_t)(b * 64 + 2 * dd + 1) * NQ + n];
        a2[dd] = pk2(a0, a1);
    }

#pragma unroll
    for (int c0 = 0; c0 < 8; c0++) {
        int cl = sub * 8 + c0;
        const ull* wr = (const ull*)(sw + cl * 64);
        ull s2 = 0ull;
#pragma unroll
        for (int dd = 0; dd < 32; dd++)
            s2 = ffma2(a2[dd], wr[dd], s2);
        float s0, s1; upk2(s2, s0, s1);
        int co = cog * 32 + cl;
        out[(size_t)(b * 128 + co) * NQ + n] += s0 + s1;
    }
}

// ---------------- launcher ---------------------------------------------------
extern "C" void kernel_launch(void* const* d_in, const int* in_sizes, int n_in,
                              void* d_out, int out_size)
{
    const float* x     = (const float*)d_in[0];
    const float* gamma = (const float*)d_in[1];
    const float* beta  = (const float*)d_in[2];
    const float* rmean = (const float*)d_in[3];
    const float* rvar  = (const float*)d_in[4];
    const float* w_sc  = (const float*)d_in[5];
    const float* w_q   = (const float*)d_in[6];
    const float* w_k   = (const float*)d_in[7];
    const float* w_v   = (const float*)d_in[8];
    const float* w_o   = (const float*)d_in[9];
    float* out = (float*)d_out;

    prep_kernel<<<2944, 256>>>(x, gamma, beta, rmean, rvar, w_sc, w_q, w_k, w_v);
    gemm_kernel<<<dim3(32, 15), 256>>>();
    gather_kernel<<<dim3(65, 4, 8), dim3(65, 4)>>>(out);
    attn2_kernel<<<dim3(34, 8, 4), 256>>>();
    proj_kernel<<<dim3(67, 4, 4), 256>>>(w_o, out);
}

// round 13
// speedup vs baseline: 1.2766x; 1.2478x over previous
#include <cuda_runtime.h>
#include <cstdint>

#define BB 4
#define CC 256
#define NQ 4225        // 65*65
#define NCO 192        // 128 shortcut + 64 q
#define MPAD 1920      // 1728 conv + 64 k + 64 v, padded to 15*128
#define NTOT 4096      // 4 b * 1024 p

typedef unsigned long long ull;

// ---------------- scratch (device globals; no allocation allowed) ------------
__device__ float g_xrT[BB * 1024 * CC];       // BN+ReLU, transposed [b][p][c] (tf32-rounded)
__device__ float g_wA[MPAD * CC];             // GEMM A rows: conv taps (flipped) + wk + wv
__device__ float g_Y[MPAD * NTOT];            // GEMM result [m][n=b*1024+p]
__device__ float g_q[BB * 64 * NQ];           // q conv output  [b][d][n]
__device__ float g_attO[BB * 64 * NQ];        // attention out  [b][d][n]

// ---------------- helpers ----------------------------------------------------
__device__ __forceinline__ ull pk2(float a, float b) {
    ull r; asm("mov.b64 %0, {%1,%2};" : "=l"(r) : "f"(a), "f"(b)); return r;
}
__device__ __forceinline__ void upk2(ull v, float& a, float& b) {
    asm("mov.b64 {%0,%1}, %2;" : "=f"(a), "=f"(b) : "l"(v));
}
__device__ __forceinline__ ull ffma2(ull a, ull b, ull c) {
    ull r; asm("fma.rn.f32x2 %0, %1, %2, %3;" : "=l"(r) : "l"(a), "l"(b), "l"(c)); return r;
}
__device__ __forceinline__ float ex2f(float x) {
    float r; asm("ex2.approx.f32 %0, %1;" : "=f"(r) : "f"(x)); return r;
}
__device__ __forceinline__ float tf32r(float x) {   // round-to-nearest tf32
    float r; asm("cvt.rna.tf32.f32 %0, %1;" : "=f"(r) : "f"(x)); return r;
}
__device__ __forceinline__ uint32_t smem_u32(const void* p) {
    return (uint32_t)__cvta_generic_to_shared(p);
}
__device__ __forceinline__ void cpasync16(uint32_t saddr, const void* g) {
    asm volatile("cp.async.cg.shared.global [%0], [%1], 16;" :: "r"(saddr), "l"(g));
}
#define CP_COMMIT() asm volatile("cp.async.commit_group;" ::: "memory")
#define CP_WAIT(n)  asm volatile("cp.async.wait_group %0;" :: "n"(n) : "memory")

// mma.sync m16n8k8 tf32. Frag layouts (PTX, verified R7/R8):
//  A: a0=(g,tg) a1=(g+8,tg) a2=(g,tg+4) a3=(g+8,tg+4)
//  B: b0=(k=tg, n=g) b1=(k=tg+4, n=g)
//  C: c0=(g,2tg) c1=(g,2tg+1) c2=(g+8,2tg) c3=(g+8,2tg+1)
__device__ __forceinline__ void mma_acc(float* d, const uint32_t* a, uint32_t b0, uint32_t b1) {
    asm volatile(
        "mma.sync.aligned.m16n8k8.row.col.f32.tf32.tf32.f32 "
        "{%0,%1,%2,%3}, {%4,%5,%6,%7}, {%8,%9}, {%0,%1,%2,%3};"
        : "+f"(d[0]), "+f"(d[1]), "+f"(d[2]), "+f"(d[3])
        : "r"(a[0]), "r"(a[1]), "r"(a[2]), "r"(a[3]), "r"(b0), "r"(b1));
}
__device__ __forceinline__ void mma_z(float* d, const uint32_t* a, uint32_t b0, uint32_t b1) {
    asm volatile(
        "mma.sync.aligned.m16n8k8.row.col.f32.tf32.tf32.f32 "
        "{%0,%1,%2,%3}, {%4,%5,%6,%7}, {%8,%9}, {%10,%11,%12,%13};"
        : "=f"(d[0]), "=f"(d[1]), "=f"(d[2]), "=f"(d[3])
        : "r"(a[0]), "r"(a[1]), "r"(a[2]), "r"(a[3]), "r"(b0), "r"(b1),
          "f"(0.f), "f"(0.f), "f"(0.f), "f"(0.f));
}
__device__ __forceinline__ void mma8(float* d, const uint32_t* a, const uint32_t* b) {
    asm volatile(
        "mma.sync.aligned.m16n8k8.row.col.f32.tf32.tf32.f32 "
        "{%0,%1,%2,%3}, {%4,%5,%6,%7}, {%8,%9}, {%0,%1,%2,%3};"
        : "+f"(d[0]), "+f"(d[1]), "+f"(d[2]), "+f"(d[3])
        : "r"(a[0]), "r"(a[1]), "r"(a[2]), "r"(a[3]), "r"(b[0]), "r"(b[1]));
}

// ---------------- kernel 1: fused prep (bnT + wpack), branch on blockIdx -----
// blocks [0,1024): BN+ReLU+transpose -> xrT.  blocks [1024,2944): weight pack.
__global__ void __launch_bounds__(256) prep_kernel(
    const float* __restrict__ x, const float* __restrict__ gamma,
    const float* __restrict__ beta, const float* __restrict__ rmean,
    const float* __restrict__ rvar,
    const float* __restrict__ w_sc, const float* __restrict__ w_q,
    const float* __restrict__ w_k, const float* __restrict__ w_v)
{
    __shared__ float s[32][33];
    const int bx = blockIdx.x;
    const int tid = threadIdx.x;
    if (bx < 1024) {
        const int pb = bx & 31, cb = (bx >> 5) & 7, b = bx >> 8;
        const int tx = tid & 31, ty = tid >> 5;       // 32 x 8
#pragma unroll
        for (int k = 0; k < 4; k++) {
            int cl = ty + k * 8;
            int c = cb * 32 + cl;
            float a = gamma[c] * rsqrtf(rvar[c] + 1e-5f);
            float bia = beta[c] - rmean[c] * a;
            float v = fmaxf(fmaf(x[(b * 256 + c) * 1024 + pb * 32 + tx], a, bia), 0.f);
            s[cl][tx] = v;
        }
        __syncthreads();
#pragma unroll
        for (int k = 0; k < 4; k++) {
            int pl = ty + k * 8;
            int p = pb * 32 + pl;
            g_xrT[(b * 1024 + p) * 256 + cb * 32 + tx] = tf32r(s[tx][pl]);
        }
    } else {
        int i = (bx - 1024) * 256 + tid;              // [0, 1920*256)
        int m = i >> 8, c = i & 255;
        float v = 0.f;
        if (m < 1728) {
            int t = m / NCO, co = m - t * NCO;
            int sfl = 8 - t;                           // spatial flip (verified)
            if (co < 128) v = w_sc[(c * 128 + co) * 9 + sfl];
            else          v = w_q[(c * 64 + (co - 128)) * 9 + sfl];
        } else if (m < 1792) {
            v = w_k[(m - 1728) * 256 + c];
        } else if (m < 1856) {
            v = w_v[(m - 1792) * 256 + c];
        }
        g_wA[i] = tf32r(v);
    }
}

// ---------------- kernel 2: cp.async double-buffered tf32 GEMM ---------------
// Y = [Wconv;Wk;Wv] x X^T. Block 128x128, 8 warps (2m x 4n).
// K=256 in 16 chunks of 16, 2-stage cp.async pipeline. SSTR=20 (bank-clean).
#define SSTR 20
__global__ void __launch_bounds__(256) gemm_kernel() {
    __shared__ __align__(16) float As[2][128 * SSTR];
    __shared__ __align__(16) float Bs[2][128 * SSTR];
    const int tid = threadIdx.x;
    const int wid = tid >> 5, lane = tid & 31;
    const int nt = blockIdx.x, mt = blockIdx.y;
    const int wm = wid & 1, wn = wid >> 1;            // 2 x 4
    const int g = lane >> 2, tg = lane & 3;

    const int lrow0 = tid >> 2, lq0 = tid & 3;        // rows 0..63
    const int lrow1 = lrow0 + 64;

    auto load_stage = [&](int kc, int buf) {
        const float* ga0 = g_wA + (size_t)(mt * 128 + lrow0) * 256 + kc * 16 + lq0 * 4;
        const float* ga1 = g_wA + (size_t)(mt * 128 + lrow1) * 256 + kc * 16 + lq0 * 4;
        const float* gb0 = g_xrT + (size_t)(nt * 128 + lrow0) * 256 + kc * 16 + lq0 * 4;
        const float* gb1 = g_xrT + (size_t)(nt * 128 + lrow1) * 256 + kc * 16 + lq0 * 4;
        cpasync16(smem_u32(&As[buf][lrow0 * SSTR + lq0 * 4]), ga0);
        cpasync16(smem_u32(&As[buf][lrow1 * SSTR + lq0 * 4]), ga1);
        cpasync16(smem_u32(&Bs[buf][lrow0 * SSTR + lq0 * 4]), gb0);
        cpasync16(smem_u32(&Bs[buf][lrow1 * SSTR + lq0 * 4]), gb1);
    };

    float acc[4][4][4];
#pragma unroll
    for (int mi = 0; mi < 4; mi++)
#pragma unroll
        for (int ni = 0; ni < 4; ni++)
#pragma unroll
            for (int q = 0; q < 4; q++) acc[mi][ni][q] = 0.f;

    load_stage(0, 0);
    CP_COMMIT();

    for (int kc = 0; kc < 16; kc++) {
        const int buf = kc & 1;
        if (kc + 1 < 16) {
            load_stage(kc + 1, buf ^ 1);
            CP_COMMIT();
            CP_WAIT(1);
        } else {
            CP_WAIT(0);
        }
        __syncthreads();

#pragma unroll
        for (int ks = 0; ks < 2; ks++) {
            uint32_t a[4][4], b[4][2];
#pragma unroll
            for (int mi = 0; mi < 4; mi++) {
                const float* ap = &As[buf][(wm * 64 + mi * 16) * SSTR + ks * 8];
                a[mi][0] = __float_as_uint(ap[g * SSTR + tg]);
                a[mi][1] = __float_as_uint(ap[(g + 8) * SSTR + tg]);
                a[mi][2] = __float_as_uint(ap[g * SSTR + tg + 4]);
                a[mi][3] = __float_as_uint(ap[(g + 8) * SSTR + tg + 4]);
            }
#pragma unroll
            for (int ni = 0; ni < 4; ni++) {
                const float* bp = &Bs[buf][(wn * 32 + ni * 8) * SSTR + ks * 8];
                b[ni][0] = __float_as_uint(bp[g * SSTR + tg]);
                b[ni][1] = __float_as_uint(bp[g * SSTR + tg + 4]);
            }
#pragma unroll
            for (int mi = 0; mi < 4; mi++)
#pragma unroll
                for (int ni = 0; ni < 4; ni++)
                    mma8(acc[mi][ni], a[mi], b[ni]);
        }
        __syncthreads();   // all reads of buf done before it is refilled (kc+2)
    }

#pragma unroll
    for (int mi = 0; mi < 4; mi++) {
#pragma unroll
        for (int ni = 0; ni < 4; ni++) {
            int row0 = mt * 128 + wm * 64 + mi * 16 + g;
            int col  = nt * 128 + wn * 32 + ni * 8 + 2 * tg;
            float2 v0 = make_float2(acc[mi][ni][0], acc[mi][ni][1]);
            float2 v1 = make_float2(acc[mi][ni][2], acc[mi][ni][3]);
            *(float2*)(g_Y + (size_t)row0 * NTOT + col) = v0;
            *(float2*)(g_Y + (size_t)(row0 + 8) * NTOT + col) = v1;
        }
    }
}

// ---------------- kernel 3: tap-gather  Y -> out(shortcut) + g_q -------------
// block (65,4): x = threadIdx.x (no integer division anywhere).
__global__ void __launch_bounds__(260) gather_kernel(float* __restrict__ out) {
    const int y = blockIdx.x, b = blockIdx.y, zg = blockIdx.z;
    const int x = threadIdx.x;                         // 0..64
    const int ty = threadIdx.y;                        // 0..3

    int tys[2], iys[2], nyy = 0;
    if (y & 1) { tys[0] = 1; iys[0] = y >> 1; nyy = 1; }
    else {
        if ((y >> 1) <= 31)    { tys[nyy] = 0; iys[nyy] = y >> 1;       nyy++; }
        if ((y >> 1) - 1 >= 0) { tys[nyy] = 2; iys[nyy] = (y >> 1) - 1; nyy++; }
    }
    int txs[2], ixs[2], nxx = 0;
    if (x & 1) { txs[0] = 1; ixs[0] = x >> 1; nxx = 1; }
    else {
        if ((x >> 1) <= 31)    { txs[nxx] = 0; ixs[nxx] = x >> 1;       nxx++; }
        if ((x >> 1) - 1 >= 0) { txs[nxx] = 2; ixs[nxx] = (x >> 1) - 1; nxx++; }
    }
    const int n = y * 65 + x;

#pragma unroll
    for (int i = 0; i < 6; i++) {
        int co = zg * 24 + i * 4 + ty;
        float s = 0.f;
        for (int yi = 0; yi < nyy; yi++)
            for (int xi = 0; xi < nxx; xi++) {
                int t = tys[yi] * 3 + txs[xi];
                s += __ldg(g_Y + (size_t)(t * NCO + co) * NTOT + b * 1024 + iys[yi] * 32 + ixs[xi]);
            }
        if (co < 128) out[(size_t)(b * 128 + co) * NQ + n] = s;
        else          g_q[(size_t)(b * 64 + (co - 128)) * NQ + n] = s;
    }
}

// ---------------- kernel 4: tensor-core attention, ZERO-shuffle P ------------
// CTA = 128 q rows x one (b,h); warp = 16 q rows. 8 chunks of 128 keys.
// V rows are PERMUTED in smem (within each 8-key block: row i holds key 2i for
// i<4, key 2(i-4)+1 for i>=4). With that permutation the QK C-fragment IS a
// valid PV A-fragment after register reorder {c0,c2,c1,c3} -- the 8 shuffles
// + 4 selects per block of R9-R11 vanish. Row sums from C-frag as before.
__global__ void __launch_bounds__(256) attn2_kernel() {
    __shared__ float sKc[128 * 9];
    __shared__ float sVc[128 * 9];
    const int qt = blockIdx.x, h = blockIdx.y, b = blockIdx.z;
    const int tid = threadIdx.x, wid = tid >> 5, lane = tid & 31;
    const int g = lane >> 2, tg = lane & 3;
    const int n0 = qt * 128 + wid * 16;
    const float sc = 0.35355339059327373f * 1.4426950408889634f;  // 1/sqrt(dk)*log2(e)

    uint32_t qf[4];
    {
        const float* qb = g_q + (size_t)(b * 64 + h * 8) * NQ;
        int nA = n0 + g, nB = n0 + 8 + g;
        float v0 = (nA < NQ) ? tf32r(qb[(size_t)tg * NQ + nA] * sc) : 0.f;
        float v1 = (nB < NQ) ? tf32r(qb[(size_t)tg * NQ + nB] * sc) : 0.f;
        float v2 = (nA < NQ) ? tf32r(qb[(size_t)(tg + 4) * NQ + nA] * sc) : 0.f;
        float v3 = (nB < NQ) ? tf32r(qb[(size_t)(tg + 4) * NQ + nB] * sc) : 0.f;
        qf[0] = __float_as_uint(v0); qf[1] = __float_as_uint(v1);
        qf[2] = __float_as_uint(v2); qf[3] = __float_as_uint(v3);
    }

    float oacc[4] = {0.f, 0.f, 0.f, 0.f};
    float lsum0 = 0.f, lsum2 = 0.f;

    const int dld = tid >> 5;                          // 0..7
    const int kq = (tid & 31) * 4;                     // 0..124
    const float* srcK = g_Y + (size_t)(1728 + h * 8 + dld) * NTOT + b * 1024 + kq;
    const float* srcV = g_Y + (size_t)(1792 + h * 8 + dld) * NTOT + b * 1024 + kq;

    // V row permutation within each 8-key block: j even -> j/2, j odd -> j/2+4
    int vrow[4];
#pragma unroll
    for (int i = 0; i < 4; i++) {
        int j = (kq + i) & 7, blk = (kq + i) >> 3;
        vrow[i] = blk * 8 + ((j & 1) ? (j >> 1) + 4 : (j >> 1));
    }

    for (int ch = 0; ch < 8; ch++) {
        __syncthreads();
        {
            float4 k4 = *(const float4*)(srcK + ch * 128);
            sKc[(kq + 0) * 9 + dld] = tf32r(k4.x);
            sKc[(kq + 1) * 9 + dld] = tf32r(k4.y);
            sKc[(kq + 2) * 9 + dld] = tf32r(k4.z);
            sKc[(kq + 3) * 9 + dld] = tf32r(k4.w);
            float4 v4 = *(const float4*)(srcV + ch * 128);
            sVc[vrow[0] * 9 + dld] = tf32r(v4.x);
            sVc[vrow[1] * 9 + dld] = tf32r(v4.y);
            sVc[vrow[2] * 9 + dld] = tf32r(v4.z);
            sVc[vrow[3] * 9 + dld] = tf32r(v4.w);
        }
        __syncthreads();

#pragma unroll
        for (int kk = 0; kk < 16; kk++) {
            // S block = Q x K^T  (16q x 8k)
            uint32_t kf0 = __float_as_uint(sKc[(kk * 8 + g) * 9 + tg]);
            uint32_t kf1 = __float_as_uint(sKc[(kk * 8 + g) * 9 + tg + 4]);
            float s[4];
            mma_z(s, qf, kf0, kf1);
            float p0 = ex2f(s[0]), p1 = ex2f(s[1]);
            float p2 = ex2f(s[2]), p3 = ex2f(s[3]);
            // row sums straight from C-fragment (rows g / g+8)
            lsum0 += p0 + p1;
            lsum2 += p2 + p3;
            // C-frag IS the A-frag under the V-row permutation: {c0,c2,c1,c3}
            uint32_t af[4];
            af[0] = __float_as_uint(p0);
            af[1] = __float_as_uint(p2);
            af[2] = __float_as_uint(p1);
            af[3] = __float_as_uint(p3);
            // O += P V
            uint32_t vb0 = __float_as_uint(sVc[(kk * 8 + tg) * 9 + g]);
            uint32_t vb1 = __float_as_uint(sVc[(kk * 8 + tg + 4) * 9 + g]);
            mma_acc(oacc, af, vb0, vb1);
        }
    }

    // reduce row sums over the 4 tg-lanes of each row group
    lsum0 += __shfl_xor_sync(0xffffffffu, lsum0, 1);
    lsum0 += __shfl_xor_sync(0xffffffffu, lsum0, 2);
    lsum2 += __shfl_xor_sync(0xffffffffu, lsum2, 1);
    lsum2 += __shfl_xor_sync(0xffffffffu, lsum2, 2);

    // epilogue: normalize, store (C layout: rows g/g+8, cols 2tg/2tg+1 = d)
    float* ob = g_attO + (size_t)(b * 64 + h * 8) * NQ;
    int nA = n0 + g, nB = n0 + 8 + g;
    if (nA < NQ) {
        float inv = 1.f / lsum0;
        ob[(size_t)(2 * tg) * NQ + nA]     = oacc[0] * inv;
        ob[(size_t)(2 * tg + 1) * NQ + nA] = oacc[1] * inv;
    }
    if (nB < NQ) {
        float inv = 1.f / lsum2;
        ob[(size_t)(2 * tg) * NQ + nB]     = oacc[2] * inv;
        ob[(size_t)(2 * tg + 1) * NQ + nB] = oacc[3] * inv;
    }
}

// ---------------- kernel 5: output projection + residual add -----------------
__global__ void __launch_bounds__(256) proj_kernel(
    const float* __restrict__ w_o, float* __restrict__ out)
{
    __shared__ float sw[32 * 64];
    const int cog = blockIdx.z, b = blockIdx.y;
    for (int i = threadIdx.x; i < 2048; i += 256) sw[i] = w_o[cog * 2048 + i];
    __syncthreads();

    const int nl = threadIdx.x & 63;
    const int sub = threadIdx.x >> 6;                  // 0..3 (8 co each)
    const int n = blockIdx.x * 64 + nl;
    if (n >= NQ) return;

    ull a2[32];
#pragma unroll
    for (int dd = 0; dd < 32; dd++) {
        float a0 = g_attO[(size_t)(b * 64 + 2 * dd) * NQ + n];
        float a1 = g_attO[(size_t)(b * 64 + 2 * dd + 1) * NQ + n];
        a2[dd] = pk2(a0, a1);
    }

#pragma unroll
    for (int c0 = 0; c0 < 8; c0++) {
        int cl = sub * 8 + c0;
        const ull* wr = (const ull*)(sw + cl * 64);
        ull s2 = 0ull;
#pragma unroll
        for (int dd = 0; dd < 32; dd++)
            s2 = ffma2(a2[dd], wr[dd], s2);
        float s0, s1; upk2(s2, s0, s1);
        int co = cog * 32 + cl;
        out[(size_t)(b * 128 + co) * NQ + n] += s0 + s1;
    }
}

// ---------------- launcher ---------------------------------------------------
extern "C" void kernel_launch(void* const* d_in, const int* in_sizes, int n_in,
                              void* d_out, int out_size)
{
    const float* x     = (const float*)d_in[0];
    const float* gamma = (const float*)d_in[1];
    const float* beta  = (const float*)d_in[2];
    const float* rmean = (const float*)d_in[3];
    const float* rvar  = (const float*)d_in[4];
    const float* w_sc  = (const float*)d_in[5];
    const float* w_q   = (const float*)d_in[6];
    const float* w_k   = (const float*)d_in[7];
    const float* w_v   = (const float*)d_in[8];
    const float* w_o   = (const float*)d_in[9];
    float* out = (float*)d_out;

    prep_kernel<<<2944, 256>>>(x, gamma, beta, rmean, rvar, w_sc, w_q, w_k, w_v);
    gemm_kernel<<<dim3(32, 15), 256>>>();
    gather_kernel<<<dim3(65, 4, 8), dim3(65, 4)>>>(out);
    attn2_kernel<<<dim3(34, 8, 4), 256>>>();
    proj_kernel<<<dim3(67, 4, 4), 256>>>(w_o, out);
}

// round 14
// speedup vs baseline: 1.3685x; 1.0720x over previous
#include <cuda_runtime.h>
#include <cstdint>

#define BB 4
#define CC 256
#define NQ 4225        // 65*65
#define NCO 192        // 128 shortcut + 64 q
#define MPAD 1920      // 1728 conv + 64 k + 64 v, padded to 15*128
#define NTOT 4096      // 4 b * 1024 p

typedef unsigned long long ull;

// ---------------- scratch (device globals; no allocation allowed) ------------
__device__ float g_xrT[BB * 1024 * CC];       // BN+ReLU, transposed [b][p][c] (tf32-rounded)
__device__ float g_wA[MPAD * CC];             // GEMM A rows: conv taps (flipped) + wk + wv
__device__ float g_Y[MPAD * NTOT];            // GEMM result [m][n=b*1024+p]
__device__ float g_q[BB * 64 * NQ];           // q conv output  [b][d][n]
__device__ float g_attO[BB * 64 * NQ];        // attention out  [b][d][n]

// ---------------- helpers ----------------------------------------------------
__device__ __forceinline__ ull pk2(float a, float b) {
    ull r; asm("mov.b64 %0, {%1,%2};" : "=l"(r) : "f"(a), "f"(b)); return r;
}
__device__ __forceinline__ void upk2(ull v, float& a, float& b) {
    asm("mov.b64 {%0,%1}, %2;" : "=f"(a), "=f"(b) : "l"(v));
}
__device__ __forceinline__ ull ffma2(ull a, ull b, ull c) {
    ull r; asm("fma.rn.f32x2 %0, %1, %2, %3;" : "=l"(r) : "l"(a), "l"(b), "l"(c)); return r;
}
__device__ __forceinline__ float ex2f(float x) {
    float r; asm("ex2.approx.f32 %0, %1;" : "=f"(r) : "f"(x)); return r;
}
__device__ __forceinline__ float tf32r(float x) {   // round-to-nearest tf32
    float r; asm("cvt.rna.tf32.f32 %0, %1;" : "=f"(r) : "f"(x)); return r;
}
__device__ __forceinline__ uint32_t smem_u32(const void* p) {
    return (uint32_t)__cvta_generic_to_shared(p);
}
__device__ __forceinline__ void cpasync16(uint32_t saddr, const void* g) {
    asm volatile("cp.async.cg.shared.global [%0], [%1], 16;" :: "r"(saddr), "l"(g));
}
#define CP_COMMIT() asm volatile("cp.async.commit_group;" ::: "memory")
#define CP_WAIT(n)  asm volatile("cp.async.wait_group %0;" :: "n"(n) : "memory")

// mma.sync m16n8k8 tf32. Frag layouts (PTX, verified R7/R8):
//  A: a0=(g,tg) a1=(g+8,tg) a2=(g,tg+4) a3=(g+8,tg+4)
//  B: b0=(k=tg, n=g) b1=(k=tg+4, n=g)
//  C: c0=(g,2tg) c1=(g,2tg+1) c2=(g+8,2tg) c3=(g+8,2tg+1)
__device__ __forceinline__ void mma_acc(float* d, const uint32_t* a, uint32_t b0, uint32_t b1) {
    asm volatile(
        "mma.sync.aligned.m16n8k8.row.col.f32.tf32.tf32.f32 "
        "{%0,%1,%2,%3}, {%4,%5,%6,%7}, {%8,%9}, {%0,%1,%2,%3};"
        : "+f"(d[0]), "+f"(d[1]), "+f"(d[2]), "+f"(d[3])
        : "r"(a[0]), "r"(a[1]), "r"(a[2]), "r"(a[3]), "r"(b0), "r"(b1));
}
__device__ __forceinline__ void mma_z(float* d, const uint32_t* a, uint32_t b0, uint32_t b1) {
    asm volatile(
        "mma.sync.aligned.m16n8k8.row.col.f32.tf32.tf32.f32 "
        "{%0,%1,%2,%3}, {%4,%5,%6,%7}, {%8,%9}, {%10,%11,%12,%13};"
        : "=f"(d[0]), "=f"(d[1]), "=f"(d[2]), "=f"(d[3])
        : "r"(a[0]), "r"(a[1]), "r"(a[2]), "r"(a[3]), "r"(b0), "r"(b1),
          "f"(0.f), "f"(0.f), "f"(0.f), "f"(0.f));
}
__device__ __forceinline__ void mma8(float* d, const uint32_t* a, const uint32_t* b) {
    asm volatile(
        "mma.sync.aligned.m16n8k8.row.col.f32.tf32.tf32.f32 "
        "{%0,%1,%2,%3}, {%4,%5,%6,%7}, {%8,%9}, {%0,%1,%2,%3};"
        : "+f"(d[0]), "+f"(d[1]), "+f"(d[2]), "+f"(d[3])
        : "r"(a[0]), "r"(a[1]), "r"(a[2]), "r"(a[3]), "r"(b[0]), "r"(b[1]));
}

// ---------------- kernel 1: fused prep (bnT + wpack), branch on blockIdx -----
// blocks [0,1024): BN+ReLU+transpose -> xrT.  blocks [1024,2944): weight pack.
__global__ void __launch_bounds__(256) prep_kernel(
    const float* __restrict__ x, const float* __restrict__ gamma,
    const float* __restrict__ beta, const float* __restrict__ rmean,
    const float* __restrict__ rvar,
    const float* __restrict__ w_sc, const float* __restrict__ w_q,
    const float* __restrict__ w_k, const float* __restrict__ w_v)
{
    __shared__ float s[32][33];
    const int bx = blockIdx.x;
    const int tid = threadIdx.x;
    if (bx < 1024) {
        const int pb = bx & 31, cb = (bx >> 5) & 7, b = bx >> 8;
        const int tx = tid & 31, ty = tid >> 5;       // 32 x 8
#pragma unroll
        for (int k = 0; k < 4; k++) {
            int cl = ty + k * 8;
            int c = cb * 32 + cl;
            float a = gamma[c] * rsqrtf(rvar[c] + 1e-5f);
            float bia = beta[c] - rmean[c] * a;
            float v = fmaxf(fmaf(x[(b * 256 + c) * 1024 + pb * 32 + tx], a, bia), 0.f);
            s[cl][tx] = v;
        }
        __syncthreads();
#pragma unroll
        for (int k = 0; k < 4; k++) {
            int pl = ty + k * 8;
            int p = pb * 32 + pl;
            g_xrT[(b * 1024 + p) * 256 + cb * 32 + tx] = tf32r(s[tx][pl]);
        }
    } else {
        int i = (bx - 1024) * 256 + tid;              // [0, 1920*256)
        int m = i >> 8, c = i & 255;
        float v = 0.f;
        if (m < 1728) {
            int t = m / NCO, co = m - t * NCO;
            int sfl = 8 - t;                           // spatial flip (verified)
            if (co < 128) v = w_sc[(c * 128 + co) * 9 + sfl];
            else          v = w_q[(c * 64 + (co - 128)) * 9 + sfl];
        } else if (m < 1792) {
            v = w_k[(m - 1728) * 256 + c];
        } else if (m < 1856) {
            v = w_v[(m - 1792) * 256 + c];
        }
        g_wA[i] = tf32r(v);
    }
}

// ---------------- kernel 2: cp.async double-buffered tf32 GEMM ---------------
// Y = [Wconv;Wk;Wv] x X^T. Block 128x128, 8 warps (2m x 4n).
// K=256 in 16 chunks of 16, 2-stage cp.async pipeline. SSTR=20 (bank-clean).
#define SSTR 20
__global__ void __launch_bounds__(256) gemm_kernel() {
    __shared__ __align__(16) float As[2][128 * SSTR];
    __shared__ __align__(16) float Bs[2][128 * SSTR];
    const int tid = threadIdx.x;
    const int wid = tid >> 5, lane = tid & 31;
    const int nt = blockIdx.x, mt = blockIdx.y;
    const int wm = wid & 1, wn = wid >> 1;            // 2 x 4
    const int g = lane >> 2, tg = lane & 3;

    const int lrow0 = tid >> 2, lq0 = tid & 3;        // rows 0..63
    const int lrow1 = lrow0 + 64;

    auto load_stage = [&](int kc, int buf) {
        const float* ga0 = g_wA + (size_t)(mt * 128 + lrow0) * 256 + kc * 16 + lq0 * 4;
        const float* ga1 = g_wA + (size_t)(mt * 128 + lrow1) * 256 + kc * 16 + lq0 * 4;
        const float* gb0 = g_xrT + (size_t)(nt * 128 + lrow0) * 256 + kc * 16 + lq0 * 4;
        const float* gb1 = g_xrT + (size_t)(nt * 128 + lrow1) * 256 + kc * 16 + lq0 * 4;
        cpasync16(smem_u32(&As[buf][lrow0 * SSTR + lq0 * 4]), ga0);
        cpasync16(smem_u32(&As[buf][lrow1 * SSTR + lq0 * 4]), ga1);
        cpasync16(smem_u32(&Bs[buf][lrow0 * SSTR + lq0 * 4]), gb0);
        cpasync16(smem_u32(&Bs[buf][lrow1 * SSTR + lq0 * 4]), gb1);
    };

    float acc[4][4][4];
#pragma unroll
    for (int mi = 0; mi < 4; mi++)
#pragma unroll
        for (int ni = 0; ni < 4; ni++)
#pragma unroll
            for (int q = 0; q < 4; q++) acc[mi][ni][q] = 0.f;

    load_stage(0, 0);
    CP_COMMIT();

    for (int kc = 0; kc < 16; kc++) {
        const int buf = kc & 1;
        if (kc + 1 < 16) {
            load_stage(kc + 1, buf ^ 1);
            CP_COMMIT();
            CP_WAIT(1);
        } else {
            CP_WAIT(0);
        }
        __syncthreads();

#pragma unroll
        for (int ks = 0; ks < 2; ks++) {
            uint32_t a[4][4], b[4][2];
#pragma unroll
            for (int mi = 0; mi < 4; mi++) {
                const float* ap = &As[buf][(wm * 64 + mi * 16) * SSTR + ks * 8];
                a[mi][0] = __float_as_uint(ap[g * SSTR + tg]);
                a[mi][1] = __float_as_uint(ap[(g + 8) * SSTR + tg]);
                a[mi][2] = __float_as_uint(ap[g * SSTR + tg + 4]);
                a[mi][3] = __float_as_uint(ap[(g + 8) * SSTR + tg + 4]);
            }
#pragma unroll
            for (int ni = 0; ni < 4; ni++) {
                const float* bp = &Bs[buf][(wn * 32 + ni * 8) * SSTR + ks * 8];
                b[ni][0] = __float_as_uint(bp[g * SSTR + tg]);
                b[ni][1] = __float_as_uint(bp[g * SSTR + tg + 4]);
            }
#pragma unroll
            for (int mi = 0; mi < 4; mi++)
#pragma unroll
                for (int ni = 0; ni < 4; ni++)
                    mma8(acc[mi][ni], a[mi], b[ni]);
        }
        __syncthreads();   // all reads of buf done before it is refilled (kc+2)
    }

#pragma unroll
    for (int mi = 0; mi < 4; mi++) {
#pragma unroll
        for (int ni = 0; ni < 4; ni++) {
            int row0 = mt * 128 + wm * 64 + mi * 16 + g;
            int col  = nt * 128 + wn * 32 + ni * 8 + 2 * tg;
            float2 v0 = make_float2(acc[mi][ni][0], acc[mi][ni][1]);
            float2 v1 = make_float2(acc[mi][ni][2], acc[mi][ni][3]);
            *(float2*)(g_Y + (size_t)row0 * NTOT + col) = v0;
            *(float2*)(g_Y + (size_t)(row0 + 8) * NTOT + col) = v1;
        }
    }
}

// ---------------- kernel 3: tap-gather  Y -> out(shortcut) + g_q -------------
// block (65,4): x = threadIdx.x (no integer division anywhere).
__global__ void __launch_bounds__(260) gather_kernel(float* __restrict__ out) {
    const int y = blockIdx.x, b = blockIdx.y, zg = blockIdx.z;
    const int x = threadIdx.x;                         // 0..64
    const int ty = threadIdx.y;                        // 0..3

    int tys[2], iys[2], nyy = 0;
    if (y & 1) { tys[0] = 1; iys[0] = y >> 1; nyy = 1; }
    else {
        if ((y >> 1) <= 31)    { tys[nyy] = 0; iys[nyy] = y >> 1;       nyy++; }
        if ((y >> 1) - 1 >= 0) { tys[nyy] = 2; iys[nyy] = (y >> 1) - 1; nyy++; }
    }
    int txs[2], ixs[2], nxx = 0;
    if (x & 1) { txs[0] = 1; ixs[0] = x >> 1; nxx = 1; }
    else {
        if ((x >> 1) <= 31)    { txs[nxx] = 0; ixs[nxx] = x >> 1;       nxx++; }
        if ((x >> 1) - 1 >= 0) { txs[nxx] = 2; ixs[nxx] = (x >> 1) - 1; nxx++; }
    }
    const int n = y * 65 + x;

#pragma unroll
    for (int i = 0; i < 6; i++) {
        int co = zg * 24 + i * 4 + ty;
        float s = 0.f;
        for (int yi = 0; yi < nyy; yi++)
            for (int xi = 0; xi < nxx; xi++) {
                int t = tys[yi] * 3 + txs[xi];
                s += __ldg(g_Y + (size_t)(t * NCO + co) * NTOT + b * 1024 + iys[yi] * 32 + ixs[xi]);
            }
        if (co < 128) out[(size_t)(b * 128 + co) * NQ + n] = s;
        else          g_q[(size_t)(b * 64 + (co - 128)) * NQ + n] = s;
    }
}

// ---------------- kernel 4: tensor-core attention, d-major K/V + LDS.64 ------
// CTA = 128 q rows x one (b,h); warp = 16 q rows. 8 chunks of 128 keys,
// 2-stage smem double buffer (1 syncthreads per chunk, LDG issued pre-compute).
// K/V stored d-major [d][key] stride 136:
//  - K frag: 2 conflict-free LDS.32 (banks 8tg+g span 0..31)
//  - V frag: 1 conflict-free LDS.64 -- with the P-as-A-frag register order
//    {c0,c2,c1,c3}, the B operand needs V[key=2tg][d=g] and V[2tg+1][g]:
//    CONSECUTIVE keys in natural order (the R13 vrow permutation composes to
//    identity in this layout).
//  - stores: 2 STS.128 per thread per chunk (was 8 STS.32).
#define AST 136
__global__ void __launch_bounds__(256) attn2_kernel() {
    __shared__ __align__(16) float sK[2][8 * AST];
    __shared__ __align__(16) float sV[2][8 * AST];
    const int qt = blockIdx.x, h = blockIdx.y, b = blockIdx.z;
    const int tid = threadIdx.x, wid = tid >> 5, lane = tid & 31;
    const int g = lane >> 2, tg = lane & 3;
    const int n0 = qt * 128 + wid * 16;
    const float sc = 0.35355339059327373f * 1.4426950408889634f;  // 1/sqrt(dk)*log2(e)

    uint32_t qf[4];
    {
        const float* qb = g_q + (size_t)(b * 64 + h * 8) * NQ;
        int nA = n0 + g, nB = n0 + 8 + g;
        float v0 = (nA < NQ) ? tf32r(qb[(size_t)tg * NQ + nA] * sc) : 0.f;
        float v1 = (nB < NQ) ? tf32r(qb[(size_t)tg * NQ + nB] * sc) : 0.f;
        float v2 = (nA < NQ) ? tf32r(qb[(size_t)(tg + 4) * NQ + nA] * sc) : 0.f;
        float v3 = (nB < NQ) ? tf32r(qb[(size_t)(tg + 4) * NQ + nB] * sc) : 0.f;
        qf[0] = __float_as_uint(v0); qf[1] = __float_as_uint(v1);
        qf[2] = __float_as_uint(v2); qf[3] = __float_as_uint(v3);
    }

    float oacc[4] = {0.f, 0.f, 0.f, 0.f};
    float lsum0 = 0.f, lsum2 = 0.f;

    const int dld = tid >> 5;                          // 0..7 (d row; uniform per warp)
    const int kq = (tid & 31) * 4;                     // 0..124
    const float* srcK = g_Y + (size_t)(1728 + h * 8 + dld) * NTOT + b * 1024 + kq;
    const float* srcV = g_Y + (size_t)(1792 + h * 8 + dld) * NTOT + b * 1024 + kq;

    auto store_chunk = [&](int buf, float4 k4, float4 v4) {
        float4 kt = make_float4(tf32r(k4.x), tf32r(k4.y), tf32r(k4.z), tf32r(k4.w));
        float4 vt = make_float4(tf32r(v4.x), tf32r(v4.y), tf32r(v4.z), tf32r(v4.w));
        *(float4*)&sK[buf][dld * AST + kq] = kt;
        *(float4*)&sV[buf][dld * AST + kq] = vt;
    };

    // prologue: chunk 0 into buffer 0
    {
        float4 k4 = *(const float4*)(srcK);
        float4 v4 = *(const float4*)(srcV);
        store_chunk(0, k4, v4);
    }
    __syncthreads();

    for (int ch = 0; ch < 8; ch++) {
        const int buf = ch & 1;
        float4 k4n, v4n;
        if (ch + 1 < 8) {                              // issue next-chunk LDGs early
            k4n = *(const float4*)(srcK + (ch + 1) * 128);
            v4n = *(const float4*)(srcV + (ch + 1) * 128);
        }

        const float* Kb = sK[buf];
        const float* Vb = sV[buf];
#pragma unroll
        for (int kk = 0; kk < 16; kk++) {
            // S block = Q x K^T  (16q x 8k); K frag rows tg / tg+4 (d-major)
            uint32_t kf0 = __float_as_uint(Kb[tg * AST + kk * 8 + g]);
            uint32_t kf1 = __float_as_uint(Kb[(tg + 4) * AST + kk * 8 + g]);
            float s[4];
            mma_z(s, qf, kf0, kf1);
            float p0 = ex2f(s[0]), p1 = ex2f(s[1]);
            float p2 = ex2f(s[2]), p3 = ex2f(s[3]);
            lsum0 += p0 + p1;
            lsum2 += p2 + p3;
            // C-frag IS the A-frag: {c0,c2,c1,c3}
            uint32_t af[4];
            af[0] = __float_as_uint(p0);
            af[1] = __float_as_uint(p2);
            af[2] = __float_as_uint(p1);
            af[3] = __float_as_uint(p3);
            // V frag: one LDS.64 of consecutive keys (2tg, 2tg+1) at d=g
            float2 vv = *(const float2*)&Vb[g * AST + kk * 8 + 2 * tg];
            mma_acc(oacc, af, __float_as_uint(vv.x), __float_as_uint(vv.y));
        }

        if (ch + 1 < 8) {
            store_chunk(buf ^ 1, k4n, v4n);
            __syncthreads();
        }
    }

    // reduce row sums over the 4 tg-lanes of each row group
    lsum0 += __shfl_xor_sync(0xffffffffu, lsum0, 1);
    lsum0 += __shfl_xor_sync(0xffffffffu, lsum0, 2);
    lsum2 += __shfl_xor_sync(0xffffffffu, lsum2, 1);
    lsum2 += __shfl_xor_sync(0xffffffffu, lsum2, 2);

    // epilogue: normalize, store (C layout: rows g/g+8, cols 2tg/2tg+1 = d)
    float* ob = g_attO + (size_t)(b * 64 + h * 8) * NQ;
    int nA = n0 + g, nB = n0 + 8 + g;
    if (nA < NQ) {
        float inv = 1.f / lsum0;
        ob[(size_t)(2 * tg) * NQ + nA]     = oacc[0] * inv;
        ob[(size_t)(2 * tg + 1) * NQ + nA] = oacc[1] * inv;
    }
    if (nB < NQ) {
        float inv = 1.f / lsum2;
        ob[(size_t)(2 * tg) * NQ + nB]     = oacc[2] * inv;
        ob[(size_t)(2 * tg + 1) * NQ + nB] = oacc[3] * inv;
    }
}

// ---------------- kernel 5: output projection + residual add -----------------
__global__ void __launch_bounds__(256) proj_kernel(
    const float* __restrict__ w_o, float* __restrict__ out)
{
    __shared__ float sw[32 * 64];
    const int cog = blockIdx.z, b = blockIdx.y;
    for (int i = threadIdx.x; i < 2048; i += 256) sw[i] = w_o[cog * 2048 + i];
    __syncthreads();

    const int nl = threadIdx.x & 63;
    const int sub = threadIdx.x >> 6;                  // 0..3 (8 co each)
    const int n = blockIdx.x * 64 + nl;
    if (n >= NQ) return;

    ull a2[32];
#pragma unroll
    for (int dd = 0; dd < 32; dd++) {
        float a0 = g_attO[(size_t)(b * 64 + 2 * dd) * NQ + n];
        float a1 = g_attO[(size_t)(b * 64 + 2 * dd + 1) * NQ + n];
        a2[dd] = pk2(a0, a1);
    }

#pragma unroll
    for (int c0 = 0; c0 < 8; c0++) {
        int cl = sub * 8 + c0;
        const ull* wr = (const ull*)(sw + cl * 64);
        ull s2 = 0ull;
#pragma unroll
        for (int dd = 0; dd < 32; dd++)
            s2 = ffma2(a2[dd], wr[dd], s2);
        float s0, s1; upk2(s2, s0, s1);
        int co = cog * 32 + cl;
        out[(size_t)(b * 128 + co) * NQ + n] += s0 + s1;
    }
}

// ---------------- launcher ---------------------------------------------------
extern "C" void kernel_launch(void* const* d_in, const int* in_sizes, int n_in,
                              void* d_out, int out_size)
{
    const float* x     = (const float*)d_in[0];
    const float* gamma = (const float*)d_in[1];
    const float* beta  = (const float*)d_in[2];
    const float* rmean = (const float*)d_in[3];
    const float* rvar  = (const float*)d_in[4];
    const float* w_sc  = (const float*)d_in[5];
    const float* w_q   = (const float*)d_in[6];
    const float* w_k   = (const float*)d_in[7];
    const float* w_v   = (const float*)d_in[8];
    const float* w_o   = (const float*)d_in[9];
    float* out = (float*)d_out;

    prep_kernel<<<2944, 256>>>(x, gamma, beta, rmean, rvar, w_sc, w_q, w_k, w_v);
    gemm_kernel<<<dim3(32, 15), 256>>>();
    gather_kernel<<<dim3(65, 4, 8), dim3(65, 4)>>>(out);
    attn2_kernel<<<dim3(34, 8, 4), 256>>>();
    proj_kernel<<<dim3(67, 4, 4), 256>>>(w_o, out);
}

// round 15
// speedup vs baseline: 1.4214x; 1.0386x over previous
#include <cuda_runtime.h>
#include <cstdint>

#define BB 4
#define CC 256
#define NQ 4225        // 65*65
#define NCO 192        // 128 shortcut + 64 q
#define MPAD 1920      // 1728 conv + 64 k + 64 v, padded to 15*128
#define NTOT 4096      // 4 b * 1024 p

typedef unsigned long long ull;

// ---------------- scratch (device globals; no allocation allowed) ------------
__device__ float g_xrT[BB * 1024 * CC];       // BN+ReLU, transposed [b][p][c] (tf32-rounded)
__device__ float g_wA[MPAD * CC];             // GEMM A rows: conv taps (flipped) + wk + wv
__device__ float g_Y[MPAD * NTOT];            // GEMM result [m][n=b*1024+p]
__device__ float g_q[BB * 64 * NQ];           // q conv output  [b][d][n]
__device__ float g_attO[BB * 64 * NQ];        // attention out  [b][d][n]

// ---------------- helpers ----------------------------------------------------
__device__ __forceinline__ ull pk2(float a, float b) {
    ull r; asm("mov.b64 %0, {%1,%2};" : "=l"(r) : "f"(a), "f"(b)); return r;
}
__device__ __forceinline__ void upk2(ull v, float& a, float& b) {
    asm("mov.b64 {%0,%1}, %2;" : "=f"(a), "=f"(b) : "l"(v));
}
__device__ __forceinline__ ull ffma2(ull a, ull b, ull c) {
    ull r; asm("fma.rn.f32x2 %0, %1, %2, %3;" : "=l"(r) : "l"(a), "l"(b), "l"(c)); return r;
}
__device__ __forceinline__ float ex2f(float x) {
    float r; asm("ex2.approx.f32 %0, %1;" : "=f"(r) : "f"(x)); return r;
}
__device__ __forceinline__ float tf32r(float x) {   // round-to-nearest tf32
    float r; asm("cvt.rna.tf32.f32 %0, %1;" : "=f"(r) : "f"(x)); return r;
}
__device__ __forceinline__ uint32_t smem_u32(const void* p) {
    return (uint32_t)__cvta_generic_to_shared(p);
}
__device__ __forceinline__ void cpasync16(uint32_t saddr, const void* g) {
    asm volatile("cp.async.cg.shared.global [%0], [%1], 16;" :: "r"(saddr), "l"(g));
}
#define CP_COMMIT() asm volatile("cp.async.commit_group;" ::: "memory")
#define CP_WAIT(n)  asm volatile("cp.async.wait_group %0;" :: "n"(n) : "memory")

// mma.sync m16n8k8 tf32. Frag layouts (PTX, verified R7/R8):
//  A: a0=(g,tg) a1=(g+8,tg) a2=(g,tg+4) a3=(g+8,tg+4)
//  B: b0=(k=tg, n=g) b1=(k=tg+4, n=g)
//  C: c0=(g,2tg) c1=(g,2tg+1) c2=(g+8,2tg) c3=(g+8,2tg+1)
__device__ __forceinline__ void mma_acc(float* d, const uint32_t* a, uint32_t b0, uint32_t b1) {
    asm volatile(
        "mma.sync.aligned.m16n8k8.row.col.f32.tf32.tf32.f32 "
        "{%0,%1,%2,%3}, {%4,%5,%6,%7}, {%8,%9}, {%0,%1,%2,%3};"
        : "+f"(d[0]), "+f"(d[1]), "+f"(d[2]), "+f"(d[3])
        : "r"(a[0]), "r"(a[1]), "r"(a[2]), "r"(a[3]), "r"(b0), "r"(b1));
}
__device__ __forceinline__ void mma_z(float* d, const uint32_t* a, uint32_t b0, uint32_t b1) {
    asm volatile(
        "mma.sync.aligned.m16n8k8.row.col.f32.tf32.tf32.f32 "
        "{%0,%1,%2,%3}, {%4,%5,%6,%7}, {%8,%9}, {%10,%11,%12,%13};"
        : "=f"(d[0]), "=f"(d[1]), "=f"(d[2]), "=f"(d[3])
        : "r"(a[0]), "r"(a[1]), "r"(a[2]), "r"(a[3]), "r"(b0), "r"(b1),
          "f"(0.f), "f"(0.f), "f"(0.f), "f"(0.f));
}
__device__ __forceinline__ void mma8(float* d, const uint32_t* a, const uint32_t* b) {
    asm volatile(
        "mma.sync.aligned.m16n8k8.row.col.f32.tf32.tf32.f32 "
        "{%0,%1,%2,%3}, {%4,%5,%6,%7}, {%8,%9}, {%0,%1,%2,%3};"
        : "+f"(d[0]), "+f"(d[1]), "+f"(d[2]), "+f"(d[3])
        : "r"(a[0]), "r"(a[1]), "r"(a[2]), "r"(a[3]), "r"(b[0]), "r"(b[1]));
}

// ---------------- kernel 1: fused prep (bnT + wpack), branch on blockIdx -----
// blocks [0,1024): BN+ReLU+transpose -> xrT.  blocks [1024,2944): weight pack.
__global__ void __launch_bounds__(256) prep_kernel(
    const float* __restrict__ x, const float* __restrict__ gamma,
    const float* __restrict__ beta, const float* __restrict__ rmean,
    const float* __restrict__ rvar,
    const float* __restrict__ w_sc, const float* __restrict__ w_q,
    const float* __restrict__ w_k, const float* __restrict__ w_v)
{
    __shared__ float s[32][33];
    const int bx = blockIdx.x;
    const int tid = threadIdx.x;
    if (bx < 1024) {
        const int pb = bx & 31, cb = (bx >> 5) & 7, b = bx >> 8;
        const int tx = tid & 31, ty = tid >> 5;       // 32 x 8
#pragma unroll
        for (int k = 0; k < 4; k++) {
            int cl = ty + k * 8;
            int c = cb * 32 + cl;
            float a = gamma[c] * rsqrtf(rvar[c] + 1e-5f);
            float bia = beta[c] - rmean[c] * a;
            float v = fmaxf(fmaf(x[(b * 256 + c) * 1024 + pb * 32 + tx], a, bia), 0.f);
            s[cl][tx] = v;
        }
        __syncthreads();
#pragma unroll
        for (int k = 0; k < 4; k++) {
            int pl = ty + k * 8;
            int p = pb * 32 + pl;
            g_xrT[(b * 1024 + p) * 256 + cb * 32 + tx] = tf32r(s[tx][pl]);
        }
    } else {
        int i = (bx - 1024) * 256 + tid;              // [0, 1920*256)
        int m = i >> 8, c = i & 255;
        float v = 0.f;
        if (m < 1728) {
            int t = m / NCO, co = m - t * NCO;
            int sfl = 8 - t;                           // spatial flip (verified)
            if (co < 128) v = w_sc[(c * 128 + co) * 9 + sfl];
            else          v = w_q[(c * 64 + (co - 128)) * 9 + sfl];
        } else if (m < 1792) {
            v = w_k[(m - 1728) * 256 + c];
        } else if (m < 1856) {
            v = w_v[(m - 1792) * 256 + c];
        }
        g_wA[i] = tf32r(v);
    }
}

// ---------------- kernel 2: cp.async double-buffered tf32 GEMM ---------------
// Y = [Wconv;Wk;Wv] x X^T. Block 128x128, 8 warps (2m x 4n).
// K=256 in 16 chunks of 16, 2-stage cp.async pipeline. SSTR=20 (bank-clean).
#define SSTR 20
__global__ void __launch_bounds__(256) gemm_kernel() {
    __shared__ __align__(16) float As[2][128 * SSTR];
    __shared__ __align__(16) float Bs[2][128 * SSTR];
    const int tid = threadIdx.x;
    const int wid = tid >> 5, lane = tid & 31;
    const int nt = blockIdx.x, mt = blockIdx.y;
    const int wm = wid & 1, wn = wid >> 1;            // 2 x 4
    const int g = lane >> 2, tg = lane & 3;

    const int lrow0 = tid >> 2, lq0 = tid & 3;        // rows 0..63
    const int lrow1 = lrow0 + 64;

    auto load_stage = [&](int kc, int buf) {
        const float* ga0 = g_wA + (size_t)(mt * 128 + lrow0) * 256 + kc * 16 + lq0 * 4;
        const float* ga1 = g_wA + (size_t)(mt * 128 + lrow1) * 256 + kc * 16 + lq0 * 4;
        const float* gb0 = g_xrT + (size_t)(nt * 128 + lrow0) * 256 + kc * 16 + lq0 * 4;
        const float* gb1 = g_xrT + (size_t)(nt * 128 + lrow1) * 256 + kc * 16 + lq0 * 4;
        cpasync16(smem_u32(&As[buf][lrow0 * SSTR + lq0 * 4]), ga0);
        cpasync16(smem_u32(&As[buf][lrow1 * SSTR + lq0 * 4]), ga1);
        cpasync16(smem_u32(&Bs[buf][lrow0 * SSTR + lq0 * 4]), gb0);
        cpasync16(smem_u32(&Bs[buf][lrow1 * SSTR + lq0 * 4]), gb1);
    };

    float acc[4][4][4];
#pragma unroll
    for (int mi = 0; mi < 4; mi++)
#pragma unroll
        for (int ni = 0; ni < 4; ni++)
#pragma unroll
            for (int q = 0; q < 4; q++) acc[mi][ni][q] = 0.f;

    load_stage(0, 0);
    CP_COMMIT();

    for (int kc = 0; kc < 16; kc++) {
        const int buf = kc & 1;
        if (kc + 1 < 16) {
            load_stage(kc + 1, buf ^ 1);
            CP_COMMIT();
            CP_WAIT(1);
        } else {
            CP_WAIT(0);
        }
        __syncthreads();

#pragma unroll
        for (int ks = 0; ks < 2; ks++) {
            uint32_t a[4][4], b[4][2];
#pragma unroll
            for (int mi = 0; mi < 4; mi++) {
                const float* ap = &As[buf][(wm * 64 + mi * 16) * SSTR + ks * 8];
                a[mi][0] = __float_as_uint(ap[g * SSTR + tg]);
                a[mi][1] = __float_as_uint(ap[(g + 8) * SSTR + tg]);
                a[mi][2] = __float_as_uint(ap[g * SSTR + tg + 4]);
                a[mi][3] = __float_as_uint(ap[(g + 8) * SSTR + tg + 4]);
            }
#pragma unroll
            for (int ni = 0; ni < 4; ni++) {
                const float* bp = &Bs[buf][(wn * 32 + ni * 8) * SSTR + ks * 8];
                b[ni][0] = __float_as_uint(bp[g * SSTR + tg]);
                b[ni][1] = __float_as_uint(bp[g * SSTR + tg + 4]);
            }
#pragma unroll
            for (int mi = 0; mi < 4; mi++)
#pragma unroll
                for (int ni = 0; ni < 4; ni++)
                    mma8(acc[mi][ni], a[mi], b[ni]);
        }
        __syncthreads();   // all reads of buf done before it is refilled (kc+2)
    }

#pragma unroll
    for (int mi = 0; mi < 4; mi++) {
#pragma unroll
        for (int ni = 0; ni < 4; ni++) {
            int row0 = mt * 128 + wm * 64 + mi * 16 + g;
            int col  = nt * 128 + wn * 32 + ni * 8 + 2 * tg;
            float2 v0 = make_float2(acc[mi][ni][0], acc[mi][ni][1]);
            float2 v1 = make_float2(acc[mi][ni][2], acc[mi][ni][3]);
            *(float2*)(g_Y + (size_t)row0 * NTOT + col) = v0;
            *(float2*)(g_Y + (size_t)(row0 + 8) * NTOT + col) = v1;
        }
    }
}

// ---------------- kernel 3: tap-gather  Y -> out(shortcut) + g_q -------------
// block (65,4): x = threadIdx.x (no integer division anywhere).
__global__ void __launch_bounds__(260) gather_kernel(float* __restrict__ out) {
    const int y = blockIdx.x, b = blockIdx.y, zg = blockIdx.z;
    const int x = threadIdx.x;                         // 0..64
    const int ty = threadIdx.y;                        // 0..3

    int tys[2], iys[2], nyy = 0;
    if (y & 1) { tys[0] = 1; iys[0] = y >> 1; nyy = 1; }
    else {
        if ((y >> 1) <= 31)    { tys[nyy] = 0; iys[nyy] = y >> 1;       nyy++; }
        if ((y >> 1) - 1 >= 0) { tys[nyy] = 2; iys[nyy] = (y >> 1) - 1; nyy++; }
    }
    int txs[2], ixs[2], nxx = 0;
    if (x & 1) { txs[0] = 1; ixs[0] = x >> 1; nxx = 1; }
    else {
        if ((x >> 1) <= 31)    { txs[nxx] = 0; ixs[nxx] = x >> 1;       nxx++; }
        if ((x >> 1) - 1 >= 0) { txs[nxx] = 2; ixs[nxx] = (x >> 1) - 1; nxx++; }
    }
    const int n = y * 65 + x;

#pragma unroll
    for (int i = 0; i < 6; i++) {
        int co = zg * 24 + i * 4 + ty;
        float s = 0.f;
        for (int yi = 0; yi < nyy; yi++)
            for (int xi = 0; xi < nxx; xi++) {
                int t = tys[yi] * 3 + txs[xi];
                s += __ldg(g_Y + (size_t)(t * NCO + co) * NTOT + b * 1024 + iys[yi] * 32 + ixs[xi]);
            }
        if (co < 128) out[(size_t)(b * 128 + co) * NQ + n] = s;
        else          g_q[(size_t)(b * 64 + (co - 128)) * NQ + n] = s;
    }
}

// ---------------- kernel 4: tensor-core attention, 2 q-tiles per warp --------
// CTA = 256 q rows x one (b,h); warp = 32 q rows (two 16-row A-frags).
// 8 chunks of 128 keys, 2-stage smem double buffer. K/V d-major stride 136.
// Per 8-key block: 3 LDS + addr arith amortized over 4 MMAs + 8 EX2
// (was per 2 MMAs + 4 EX2) -> ~30% fewer issue slots per unit work.
#define AST 136
__global__ void __launch_bounds__(256) attn2_kernel() {
    __shared__ __align__(16) float sK[2][8 * AST];
    __shared__ __align__(16) float sV[2][8 * AST];
    const int qt = blockIdx.x, h = blockIdx.y, b = blockIdx.z;
    const int tid = threadIdx.x, wid = tid >> 5, lane = tid & 31;
    const int g = lane >> 2, tg = lane & 3;
    const int n0 = qt * 256 + wid * 32;
    const float sc = 0.35355339059327373f * 1.4426950408889634f;  // 1/sqrt(dk)*log2(e)

    uint32_t qf[2][4];
    {
        const float* qb = g_q + (size_t)(b * 64 + h * 8) * NQ;
#pragma unroll
        for (int t = 0; t < 2; t++) {
            int nA = n0 + t * 16 + g, nB = nA + 8;
            float v0 = (nA < NQ) ? tf32r(qb[(size_t)tg * NQ + nA] * sc) : 0.f;
            float v1 = (nB < NQ) ? tf32r(qb[(size_t)tg * NQ + nB] * sc) : 0.f;
            float v2 = (nA < NQ) ? tf32r(qb[(size_t)(tg + 4) * NQ + nA] * sc) : 0.f;
            float v3 = (nB < NQ) ? tf32r(qb[(size_t)(tg + 4) * NQ + nB] * sc) : 0.f;
            qf[t][0] = __float_as_uint(v0); qf[t][1] = __float_as_uint(v1);
            qf[t][2] = __float_as_uint(v2); qf[t][3] = __float_as_uint(v3);
        }
    }

    float oacc[2][4] = {{0.f, 0.f, 0.f, 0.f}, {0.f, 0.f, 0.f, 0.f}};
    float lsum0[2] = {0.f, 0.f}, lsum2[2] = {0.f, 0.f};

    const int dld = tid >> 5;                          // 0..7 (d row; uniform per warp)
    const int kq = (tid & 31) * 4;                     // 0..124
    const float* srcK = g_Y + (size_t)(1728 + h * 8 + dld) * NTOT + b * 1024 + kq;
    const float* srcV = g_Y + (size_t)(1792 + h * 8 + dld) * NTOT + b * 1024 + kq;

    auto store_chunk = [&](int buf, float4 k4, float4 v4) {
        float4 kt = make_float4(tf32r(k4.x), tf32r(k4.y), tf32r(k4.z), tf32r(k4.w));
        float4 vt = make_float4(tf32r(v4.x), tf32r(v4.y), tf32r(v4.z), tf32r(v4.w));
        *(float4*)&sK[buf][dld * AST + kq] = kt;
        *(float4*)&sV[buf][dld * AST + kq] = vt;
    };

    // prologue: chunk 0 into buffer 0
    {
        float4 k4 = *(const float4*)(srcK);
        float4 v4 = *(const float4*)(srcV);
        store_chunk(0, k4, v4);
    }
    __syncthreads();

    for (int ch = 0; ch < 8; ch++) {
        const int buf = ch & 1;
        float4 k4n, v4n;
        if (ch + 1 < 8) {                              // issue next-chunk LDGs early
            k4n = *(const float4*)(srcK + (ch + 1) * 128);
            v4n = *(const float4*)(srcV + (ch + 1) * 128);
        }

        const float* Kb = sK[buf];
        const float* Vb = sV[buf];
#pragma unroll
        for (int kk = 0; kk < 16; kk++) {
            // shared K/V fragments for both q-tiles
            uint32_t kf0 = __float_as_uint(Kb[tg * AST + kk * 8 + g]);
            uint32_t kf1 = __float_as_uint(Kb[(tg + 4) * AST + kk * 8 + g]);
            float2 vv = *(const float2*)&Vb[g * AST + kk * 8 + 2 * tg];
            uint32_t vb0 = __float_as_uint(vv.x), vb1 = __float_as_uint(vv.y);
#pragma unroll
            for (int t = 0; t < 2; t++) {
                float s[4];
                mma_z(s, qf[t], kf0, kf1);
                float p0 = ex2f(s[0]), p1 = ex2f(s[1]);
                float p2 = ex2f(s[2]), p3 = ex2f(s[3]);
                lsum0[t] += p0 + p1;
                lsum2[t] += p2 + p3;
                // C-frag IS the A-frag: {c0,c2,c1,c3}
                uint32_t af[4];
                af[0] = __float_as_uint(p0);
                af[1] = __float_as_uint(p2);
                af[2] = __float_as_uint(p1);
                af[3] = __float_as_uint(p3);
                mma_acc(oacc[t], af, vb0, vb1);
            }
        }

        if (ch + 1 < 8) {
            store_chunk(buf ^ 1, k4n, v4n);
            __syncthreads();
        }
    }

    // reduce row sums over the 4 tg-lanes of each row group
#pragma unroll
    for (int t = 0; t < 2; t++) {
        lsum0[t] += __shfl_xor_sync(0xffffffffu, lsum0[t], 1);
        lsum0[t] += __shfl_xor_sync(0xffffffffu, lsum0[t], 2);
        lsum2[t] += __shfl_xor_sync(0xffffffffu, lsum2[t], 1);
        lsum2[t] += __shfl_xor_sync(0xffffffffu, lsum2[t], 2);
    }

    // epilogue: normalize, store (C layout: rows g/g+8, cols 2tg/2tg+1 = d)
    float* ob = g_attO + (size_t)(b * 64 + h * 8) * NQ;
#pragma unroll
    for (int t = 0; t < 2; t++) {
        int nA = n0 + t * 16 + g, nB = nA + 8;
        if (nA < NQ) {
            float inv = 1.f / lsum0[t];
            ob[(size_t)(2 * tg) * NQ + nA]     = oacc[t][0] * inv;
            ob[(size_t)(2 * tg + 1) * NQ + nA] = oacc[t][1] * inv;
        }
        if (nB < NQ) {
            float inv = 1.f / lsum2[t];
            ob[(size_t)(2 * tg) * NQ + nB]     = oacc[t][2] * inv;
            ob[(size_t)(2 * tg + 1) * NQ + nB] = oacc[t][3] * inv;
        }
    }
}

// ---------------- kernel 5: output projection + residual add -----------------
__global__ void __launch_bounds__(256) proj_kernel(
    const float* __restrict__ w_o, float* __restrict__ out)
{
    __shared__ float sw[32 * 64];
    const int cog = blockIdx.z, b = blockIdx.y;
    for (int i = threadIdx.x; i < 2048; i += 256) sw[i] = w_o[cog * 2048 + i];
    __syncthreads();

    const int nl = threadIdx.x & 63;
    const int sub = threadIdx.x >> 6;                  // 0..3 (8 co each)
    const int n = blockIdx.x * 64 + nl;
    if (n >= NQ) return;

    ull a2[32];
#pragma unroll
    for (int dd = 0; dd < 32; dd++) {
        float a0 = g_attO[(size_t)(b * 64 + 2 * dd) * NQ + n];
        float a1 = g_attO[(size_t)(b * 64 + 2 * dd + 1) * NQ + n];
        a2[dd] = pk2(a0, a1);
    }

#pragma unroll
    for (int c0 = 0; c0 < 8; c0++) {
        int cl = sub * 8 + c0;
        const ull* wr = (const ull*)(sw + cl * 64);
        ull s2 = 0ull;
#pragma unroll
        for (int dd = 0; dd < 32; dd++)
            s2 = ffma2(a2[dd], wr[dd], s2);
        float s0, s1; upk2(s2, s0, s1);
        int co = cog * 32 + cl;
        out[(size_t)(b * 128 + co) * NQ + n] += s0 + s1;
    }
}

// ---------------- launcher ---------------------------------------------------
extern "C" void kernel_launch(void* const* d_in, const int* in_sizes, int n_in,
                              void* d_out, int out_size)
{
    const float* x     = (const float*)d_in[0];
    const float* gamma = (const float*)d_in[1];
    const float* beta  = (const float*)d_in[2];
    const float* rmean = (const float*)d_in[3];
    const float* rvar  = (const float*)d_in[4];
    const float* w_sc  = (const float*)d_in[5];
    const float* w_q   = (const float*)d_in[6];
    const float* w_k   = (const float*)d_in[7];
    const float* w_v   = (const float*)d_in[8];
    const float* w_o   = (const float*)d_in[9];
    float* out = (float*)d_out;

    prep_kernel<<<2944, 256>>>(x, gamma, beta, rmean, rvar, w_sc, w_q, w_k, w_v);
    gemm_kernel<<<dim3(32, 15), 256>>>();
    gather_kernel<<<dim3(65, 4, 8), dim3(65, 4)>>>(out);
    attn2_kernel<<<dim3(17, 8, 4), 256>>>();
    proj_kernel<<<dim3(67, 4, 4), 256>>>(w_o, out);
}